// round 9
// baseline (speedup 1.0000x reference)
#include <cuda_runtime.h>
#include <cuda_bf16.h>
#include <math.h>
#include <stdint.h>

#define N_PTS 32768
typedef uint32_t u32;

// ---------------- scratch (device globals; no allocations allowed) ----------
__device__ float g_bufA[N_PTS * 256];
__device__ float g_bufB[N_PTS * 256];
__device__ __align__(16) __nv_bfloat16 g_W0h[256 * 288],  g_W0l[256 * 288];
__device__ __align__(16) __nv_bfloat16 g_W1h[256 * 2304], g_W1l[256 * 2304];
__device__ __align__(16) __nv_bfloat16 g_W2h[256 * 2304], g_W2l[256 * 2304];
__device__ float g_w3[2304];

// ---------------- PTX helpers (compute_80-era, arch-neutral) -----------------
__device__ __forceinline__ u32 smem_u32(const void* p) {
    u32 a;
    asm("{ .reg .u64 t; cvta.to.shared.u64 t, %1; cvt.u32.u64 %0, t; }"
        : "=r"(a) : "l"(p));
    return a;
}
__device__ __forceinline__ void ldsm_x4(u32* r, u32 addr) {
    asm volatile("ldmatrix.sync.aligned.m8n8.x4.shared.b16 {%0,%1,%2,%3}, [%4];"
                 : "=r"(r[0]), "=r"(r[1]), "=r"(r[2]), "=r"(r[3]) : "r"(addr));
}
__device__ __forceinline__ void mma_bf16(float* c, const u32* a, const u32* b) {
    asm volatile(
        "mma.sync.aligned.m16n8k16.row.col.f32.bf16.bf16.f32 "
        "{%0,%1,%2,%3}, {%4,%5,%6,%7}, {%8,%9}, {%0,%1,%2,%3};"
        : "+f"(c[0]), "+f"(c[1]), "+f"(c[2]), "+f"(c[3])
        : "r"(a[0]), "r"(a[1]), "r"(a[2]), "r"(a[3]), "r"(b[0]), "r"(b[1]));
}
__device__ __forceinline__ void cp16(u32 dst, const void* src) {
    asm volatile("cp.async.cg.shared.global [%0], [%1], 16;"
                 :: "r"(dst), "l"(src) : "memory");
}

// ---------------- closed-form cubic B-spline (uniform knots) -----------------
__device__ __forceinline__ void bspline8(float t, float* bb) {
    float u = (t + 2.2f) * 2.5f;
    float fj = floorf(u);
    int jc = (int)fj;
    float w = u - fj;
    float om = 1.0f - w;
    float w2 = w * w, w3 = w2 * w;
    float p0 = om * om * om * (1.0f / 6.0f);
    float p1 = (3.0f * w3 - 6.0f * w2 + 4.0f) * (1.0f / 6.0f);
    float p2 = (-3.0f * w3 + 3.0f * w2 + 3.0f * w + 1.0f) * (1.0f / 6.0f);
    float p3 = w3 * (1.0f / 6.0f);
#pragma unroll
    for (int i = 0; i < 8; i++) {
        int m = i - jc + 3;
        float v = (m == 0) ? p0 : (m == 1) ? p1 : (m == 2) ? p2 : (m == 3) ? p3 : 0.0f;
        bb[i] = v;
    }
}
__device__ __forceinline__ float silu_f(float v) {
    return v * (1.0f / (1.0f + __expf(-v)));
}

// ---------------- fused weight prep (single launch) --------------------------
// K layout PERMUTED per 144-chunk: k = c*144 + j*16 + fl, feature f = c*16+fl.
__device__ __forceinline__ void prep_one(const float* bw, const float* sw,
                                         const float* ss,
                                         __nv_bfloat16* Wh, __nv_bfloat16* Wl,
                                         int F, int idx) {
    int K = 9 * F;
    if (idx >= 256 * K) return;
    int o = idx / K, k = idx - o * K;
    int c = k / 144, r = k - c * 144;
    int j = r >> 4, fl = r & 15;
    int f = c * 16 + fl;
    float v = (j == 0) ? bw[o * F + f] : sw[(o * F + f) * 8 + (j - 1)] * ss[o * F + f];
    __nv_bfloat16 hi = __float2bfloat16(v);
    Wh[idx] = hi;
    Wl[idx] = __float2bfloat16(v - __bfloat162float(hi));
}
__global__ void prep_all(const float* __restrict__ bw0, const float* __restrict__ sw0, const float* __restrict__ ss0,
                         const float* __restrict__ bw1, const float* __restrict__ sw1, const float* __restrict__ ss1,
                         const float* __restrict__ bw2, const float* __restrict__ sw2, const float* __restrict__ ss2,
                         const float* __restrict__ bw3, const float* __restrict__ sw3, const float* __restrict__ ss3,
                         __nv_bfloat16* __restrict__ W0h, __nv_bfloat16* __restrict__ W0l,
                         __nv_bfloat16* __restrict__ W1h, __nv_bfloat16* __restrict__ W1l,
                         __nv_bfloat16* __restrict__ W2h, __nv_bfloat16* __restrict__ W2l,
                         float* __restrict__ w3) {
    int b = blockIdx.x, t = threadIdx.x;
    if (b < 288) {
        prep_one(bw0, sw0, ss0, W0h, W0l, 32, b * 256 + t);
    } else if (b < 2592) {
        prep_one(bw1, sw1, ss1, W1h, W1l, 256, (b - 288) * 256 + t);
    } else if (b < 4896) {
        prep_one(bw2, sw2, ss2, W2h, W2l, 256, (b - 2592) * 256 + t);
    } else {
        int k = (b - 4896) * 256 + t;
        if (k < 2304) {
            int f = k / 9, j = k - f * 9;
            w3[k] = (j == 0) ? bw3[f] : sw3[f * 8 + (j - 1)] * ss3[f];
        }
    }
}

// ---------------- positional encoding ---------------------------------------
__global__ void encode_kernel(const float* __restrict__ x,
                              const float* __restrict__ freq,
                              float* __restrict__ h0) {
    int idx = blockIdx.x * blockDim.x + threadIdx.x;
    if (idx >= N_PTS * 16) return;
    int n = idx >> 4, j = idx & 15;
    float enc = x[n] * freq[j];
    double ed = (double)enc;
    double q = rint(ed * 0.15915494309189535);
    double rd = fma(-q, 6.283185307179586, ed);
    float r = (float)rd;
    float s, c;
    __sincosf(r, &s, &c);
    h0[n * 32 + j] = s;
    h0[n * 32 + 16 + j] = c;
}

// ---------------- smem swizzle: row stride 288 B (18 x 16B units) ------------
__device__ __forceinline__ u32 swz_off(int row, int u) {
    if (u < 16) return (u32)(row * 288 + ((u * 16) ^ ((row & 7) * 16)));
    return (u32)(row * 288 + 256 + (((u ^ row) & 1) * 16));
}

// ---------------- fused HMMA KAN layer, 2-stage pipelined --------------------
// CTA tile: 64 rows x 128 cols. K chunks of 144 (16 features, k = j*16+fl).
// Stage (110592 B): Ah@0 Al@18432 Wh@36864 Wl@73728. 2 stages = 221184 B.
template <int F>
__global__ void __launch_bounds__(256, 1)
kan_hmma(const float* __restrict__ hin,
         const __nv_bfloat16* __restrict__ Wh, const __nv_bfloat16* __restrict__ Wl,
         float* __restrict__ out) {
    constexpr int K = 9 * F, NCH = K / 144;
    constexpr u32 STG = 110592;
    constexpr u32 AH = 0, AL = 18432, WHo = 36864, WLo = 73728;
    extern __shared__ __align__(16) char smem[];
    const u32 sbase = smem_u32(smem);

    const int tid = threadIdx.x;
    const int lane = tid & 31, warp = tid >> 5;
    const int wm = (warp & 1) * 32;              // 2 m-groups of 32 rows
    const int wn = (warp >> 1) * 32;             // 4 n-groups of 32 cols
    const int row0 = blockIdx.x * 64;
    const int n0 = blockIdx.y * 128;

    int rowA[2], rowB[2];
    const int bitA = lane >> 4;
    const int bitB = (lane >> 3) & 1;
#pragma unroll
    for (int mi = 0; mi < 2; mi++) rowA[mi] = wm + mi * 16 + (lane & 15);
#pragma unroll
    for (int jj = 0; jj < 2; jj++) rowB[jj] = wn + jj * 16 + (lane & 7) + ((lane >> 4) << 3);

    float acc[2][4][4];
#pragma unroll
    for (int mi = 0; mi < 2; mi++)
#pragma unroll
        for (int nf = 0; nf < 4; nf++)
#pragma unroll
            for (int q = 0; q < 4; q++) acc[mi][nf][q] = 0.0f;

    // -- stage fill helpers
    auto issueW = [&](int c, u32 sb) {
#pragma unroll
        for (int i = 0; i < 9; i++) {
            int u = tid + 256 * i;
            int row = u / 18, pos = u - row * 18;
            size_t gi = ((size_t)(n0 + row) * K + c * 144) / 8 + pos;
            u32 off = swz_off(row, pos);
            cp16(sbase + sb + WHo + off, reinterpret_cast<const uint4*>(Wh) + gi);
            cp16(sbase + sb + WLo + off, reinterpret_cast<const uint4*>(Wl) + gi);
        }
    };
    auto produceA = [&](int c, u32 sb, int half) {
#pragma unroll
        for (int i = 0; i < 2; i++) {
            int id = tid + 256 * (half * 2 + i);
            int fl = id & 15, row = id >> 4;      // row 0..63
            float t = hin[(size_t)(row0 + row) * F + c * 16 + fl];
            float v[9];
            v[0] = silu_f(t);
            bspline8(t, v + 1);
            const int ub = fl >> 3, bo = (fl & 7) * 2;
#pragma unroll
            for (int j = 0; j < 9; j++) {
                u32 off = swz_off(row, 2 * j + ub) + bo;
                __nv_bfloat16 hi = __float2bfloat16(v[j]);
                *reinterpret_cast<__nv_bfloat16*>(smem + sb + AH + off) = hi;
                *reinterpret_cast<__nv_bfloat16*>(smem + sb + AL + off) =
                    __float2bfloat16(v[j] - __bfloat162float(hi));
            }
        }
    };

    // -- prologue: stage 0
    issueW(0, 0);
    asm volatile("cp.async.commit_group;" ::: "memory");
    produceA(0, 0, 0);
    produceA(0, 0, 1);

    for (int c = 0; c < NCH; c++) {
        const u32 sb = (u32)(c & 1) * STG;
        const u32 sbn = (u32)((c + 1) & 1) * STG;
        asm volatile("cp.async.wait_group 0;" ::: "memory");
        __syncthreads();                          // W(c)+A(c) visible; stage sbn free
        const bool more = (c + 1 < NCH);
        if (more) {
            issueW(c + 1, sbn);
            asm volatile("cp.async.commit_group;" ::: "memory");
        }
#pragma unroll
        for (int ks = 0; ks < 9; ks++) {
            u32 ah[2][4], al[2][4], bh[2][4], bl[2][4];
#pragma unroll
            for (int mi = 0; mi < 2; mi++) {
                u32 off = swz_off(rowA[mi], 2 * ks + bitA);
                ldsm_x4(ah[mi], sbase + sb + AH + off);
                ldsm_x4(al[mi], sbase + sb + AL + off);
            }
#pragma unroll
            for (int jj = 0; jj < 2; jj++) {
                u32 off = swz_off(rowB[jj], 2 * ks + bitB);
                ldsm_x4(bh[jj], sbase + sb + WHo + off);
                ldsm_x4(bl[jj], sbase + sb + WLo + off);
            }
#pragma unroll
            for (int mi = 0; mi < 2; mi++)
#pragma unroll
                for (int nf = 0; nf < 4; nf++) {
                    const u32* Bh = &bh[nf >> 1][(nf & 1) * 2];
                    const u32* Bl = &bl[nf >> 1][(nf & 1) * 2];
                    mma_bf16(acc[mi][nf], ah[mi], Bh);
                    mma_bf16(acc[mi][nf], ah[mi], Bl);
                    mma_bf16(acc[mi][nf], al[mi], Bh);
                }
            // interleave next-chunk A production under the MMA window
            if (more && ks == 0) produceA(c + 1, sbn, 0);
            if (more && ks == 4) produceA(c + 1, sbn, 1);
        }
    }
    // ---- epilogue: c-frag direct stores
#pragma unroll
    for (int mi = 0; mi < 2; mi++)
#pragma unroll
        for (int nf = 0; nf < 4; nf++) {
            int r0 = row0 + wm + mi * 16 + (lane >> 2);
            int cc = n0 + wn + nf * 8 + (lane & 3) * 2;
            *reinterpret_cast<float2*>(&out[(size_t)r0 * 256 + cc]) =
                make_float2(acc[mi][nf][0], acc[mi][nf][1]);
            *reinterpret_cast<float2*>(&out[(size_t)(r0 + 8) * 256 + cc]) =
                make_float2(acc[mi][nf][2], acc[mi][nf][3]);
        }
}

// ---------------- last layer: O = 1 ------------------------------------------
__global__ void kan_last(const float* __restrict__ hin,
                         const float* __restrict__ W,
                         float* __restrict__ out) {
    __shared__ float Ws[2304];
    int tid = threadIdx.x;
#pragma unroll
    for (int i = tid; i < 2304; i += 256) Ws[i] = W[i];
    __syncthreads();
    int warp = tid >> 5, lane = tid & 31;
    int n = blockIdx.x * 8 + warp;
    float sum = 0.0f;
#pragma unroll
    for (int ff = 0; ff < 8; ff++) {
        int f = ff * 32 + lane;
        float t = hin[n * 256 + f];
        float bb[8];
        bspline8(t, bb);
        float sl = silu_f(t) * Ws[f * 9];
#pragma unroll
        for (int j = 0; j < 8; j++) sl += bb[j] * Ws[f * 9 + 1 + j];
        sum += sl;
    }
#pragma unroll
    for (int off = 16; off; off >>= 1)
        sum += __shfl_xor_sync(0xffffffffu, sum, off);
    if (lane == 0) out[n] = sum;
}

// ---------------- launch ------------------------------------------------------
extern "C" void kernel_launch(void* const* d_in, const int* in_sizes, int n_in,
                              void* d_out, int out_size) {
    const float* x    = (const float*)d_in[0];
    const float* freq = (const float*)d_in[1];
    const float* bw0  = (const float*)d_in[2];
    const float* sw0  = (const float*)d_in[3];
    const float* ss0  = (const float*)d_in[4];
    const float* bw1  = (const float*)d_in[5];
    const float* sw1  = (const float*)d_in[6];
    const float* ss1  = (const float*)d_in[7];
    const float* bw2  = (const float*)d_in[8];
    const float* sw2  = (const float*)d_in[9];
    const float* ss2  = (const float*)d_in[10];
    const float* bw3  = (const float*)d_in[11];
    const float* sw3  = (const float*)d_in[12];
    const float* ss3  = (const float*)d_in[13];
    float* out = (float*)d_out;

    float *bufA, *bufB, *w3;
    __nv_bfloat16 *W0h, *W0l, *W1h, *W1l, *W2h, *W2l;
    cudaGetSymbolAddress((void**)&bufA, g_bufA);
    cudaGetSymbolAddress((void**)&bufB, g_bufB);
    cudaGetSymbolAddress((void**)&W0h, g_W0h);
    cudaGetSymbolAddress((void**)&W0l, g_W0l);
    cudaGetSymbolAddress((void**)&W1h, g_W1h);
    cudaGetSymbolAddress((void**)&W1l, g_W1l);
    cudaGetSymbolAddress((void**)&W2h, g_W2h);
    cudaGetSymbolAddress((void**)&W2l, g_W2l);
    cudaGetSymbolAddress((void**)&w3, g_w3);

    const int SMEM = 221184;
    cudaFuncSetAttribute(kan_hmma<32>,  cudaFuncAttributeMaxDynamicSharedMemorySize, SMEM);
    cudaFuncSetAttribute(kan_hmma<256>, cudaFuncAttributeMaxDynamicSharedMemorySize, SMEM);

    // [0] all weight prep in one launch
    prep_all<<<4905, 256>>>(bw0, sw0, ss0, bw1, sw1, ss1, bw2, sw2, ss2,
                            bw3, sw3, ss3, W0h, W0l, W1h, W1l, W2h, W2l, w3);
    // [1] encoding
    encode_kernel<<<(N_PTS * 16) / 256, 256>>>(x, freq, bufA);

    dim3 grid(N_PTS / 64, 2);
    // [2] layer 0
    kan_hmma<32><<<grid, 256, SMEM>>>(bufA, W0h, W0l, bufB);
    // [3] layer 1  (<- ncu capture slot)
    kan_hmma<256><<<grid, 256, SMEM>>>(bufB, W1h, W1l, bufA);
    // [4] layer 2
    kan_hmma<256><<<grid, 256, SMEM>>>(bufA, W2h, W2l, bufB);
    // [5] last layer
    kan_last<<<N_PTS / 8, 256>>>(bufB, w3, out);
}

// round 10
// speedup vs baseline: 2.1341x; 2.1341x over previous
#include <cuda_runtime.h>
#include <cuda_fp16.h>
#include <math.h>
#include <stdint.h>

#define N_PTS 32768
typedef uint32_t u32;

// ---------------- scratch (device globals; no allocations allowed) ----------
__device__ float g_bufA[N_PTS * 256];
__device__ float g_bufB[N_PTS * 256];
__device__ __align__(16) __half g_W0[256 * 288];
__device__ __align__(16) __half g_W1[256 * 2304];
__device__ __align__(16) __half g_W2[256 * 2304];
__device__ float g_w3[2304];

// ---------------- PTX helpers (compute_80-era, arch-neutral) -----------------
__device__ __forceinline__ u32 smem_u32(const void* p) {
    u32 a;
    asm("{ .reg .u64 t; cvta.to.shared.u64 t, %1; cvt.u32.u64 %0, t; }"
        : "=r"(a) : "l"(p));
    return a;
}
__device__ __forceinline__ void ldsm_x4(u32* r, u32 addr) {
    asm volatile("ldmatrix.sync.aligned.m8n8.x4.shared.b16 {%0,%1,%2,%3}, [%4];"
                 : "=r"(r[0]), "=r"(r[1]), "=r"(r[2]), "=r"(r[3]) : "r"(addr));
}
__device__ __forceinline__ void mma_f16(float* c, const u32* a, const u32* b) {
    asm volatile(
        "mma.sync.aligned.m16n8k16.row.col.f32.f16.f16.f32 "
        "{%0,%1,%2,%3}, {%4,%5,%6,%7}, {%8,%9}, {%0,%1,%2,%3};"
        : "+f"(c[0]), "+f"(c[1]), "+f"(c[2]), "+f"(c[3])
        : "r"(a[0]), "r"(a[1]), "r"(a[2]), "r"(a[3]), "r"(b[0]), "r"(b[1]));
}
__device__ __forceinline__ void cp16(u32 dst, const void* src) {
    asm volatile("cp.async.cg.shared.global [%0], [%1], 16;"
                 :: "r"(dst), "l"(src) : "memory");
}

// ---------------- closed-form cubic B-spline (uniform knots) -----------------
__device__ __forceinline__ void bspline8(float t, float* bb) {
    float u = (t + 2.2f) * 2.5f;
    float fj = floorf(u);
    int jc = (int)fj;
    float w = u - fj;
    float om = 1.0f - w;
    float w2 = w * w, w3 = w2 * w;
    float p0 = om * om * om * (1.0f / 6.0f);
    float p1 = (3.0f * w3 - 6.0f * w2 + 4.0f) * (1.0f / 6.0f);
    float p2 = (-3.0f * w3 + 3.0f * w2 + 3.0f * w + 1.0f) * (1.0f / 6.0f);
    float p3 = w3 * (1.0f / 6.0f);
#pragma unroll
    for (int i = 0; i < 8; i++) {
        int m = i - jc + 3;
        float v = (m == 0) ? p0 : (m == 1) ? p1 : (m == 2) ? p2 : (m == 3) ? p3 : 0.0f;
        bb[i] = v;
    }
}
__device__ __forceinline__ float silu_f(float v) {
    return v * (1.0f / (1.0f + __expf(-v)));
}

// ---------------- fused weight prep (single launch) --------------------------
// K layout PERMUTED per 144-chunk: k = c*144 + j*16 + fl, feature f = c*16+fl.
__device__ __forceinline__ void prep_one(const float* bw, const float* sw,
                                         const float* ss, __half* W,
                                         int F, int idx) {
    int K = 9 * F;
    if (idx >= 256 * K) return;
    int o = idx / K, k = idx - o * K;
    int c = k / 144, r = k - c * 144;
    int j = r >> 4, fl = r & 15;
    int f = c * 16 + fl;
    float v = (j == 0) ? bw[o * F + f] : sw[(o * F + f) * 8 + (j - 1)] * ss[o * F + f];
    W[idx] = __float2half_rn(v);
}
__global__ void prep_all(const float* __restrict__ bw0, const float* __restrict__ sw0, const float* __restrict__ ss0,
                         const float* __restrict__ bw1, const float* __restrict__ sw1, const float* __restrict__ ss1,
                         const float* __restrict__ bw2, const float* __restrict__ sw2, const float* __restrict__ ss2,
                         const float* __restrict__ bw3, const float* __restrict__ sw3, const float* __restrict__ ss3,
                         __half* __restrict__ W0, __half* __restrict__ W1, __half* __restrict__ W2,
                         float* __restrict__ w3) {
    int b = blockIdx.x, t = threadIdx.x;
    if (b < 288) {
        prep_one(bw0, sw0, ss0, W0, 32, b * 256 + t);
    } else if (b < 2592) {
        prep_one(bw1, sw1, ss1, W1, 256, (b - 288) * 256 + t);
    } else if (b < 4896) {
        prep_one(bw2, sw2, ss2, W2, 256, (b - 2592) * 256 + t);
    } else {
        int k = (b - 4896) * 256 + t;
        if (k < 2304) {
            int f = k / 9, j = k - f * 9;
            w3[k] = (j == 0) ? bw3[f] : sw3[f * 8 + (j - 1)] * ss3[f];
        }
    }
}

// ---------------- positional encoding ---------------------------------------
__global__ void encode_kernel(const float* __restrict__ x,
                              const float* __restrict__ freq,
                              float* __restrict__ h0) {
    int idx = blockIdx.x * blockDim.x + threadIdx.x;
    if (idx >= N_PTS * 16) return;
    int n = idx >> 4, j = idx & 15;
    float enc = x[n] * freq[j];
    double ed = (double)enc;
    double q = rint(ed * 0.15915494309189535);
    double rd = fma(-q, 6.283185307179586, ed);
    float r = (float)rd;
    float s, c;
    __sincosf(r, &s, &c);
    h0[n * 32 + j] = s;
    h0[n * 32 + 16 + j] = c;
}

// ---------------- smem swizzle: row stride 288 B (18 x 16B units) ------------
__device__ __forceinline__ u32 swz_off(int row, int u) {
    if (u < 16) return (u32)(row * 288 + ((u * 16) ^ ((row & 7) * 16)));
    return (u32)(row * 288 + 256 + (((u ^ row) & 1) * 16));
}

// ---------------- fused HMMA KAN layer ---------------------------------------
// fp16 2-term: a*w = (a_hi + a_lo) * w_fp16.
// CTA tile: 64 rows x 256 cols (FULL N). K chunks of 144 (k = j*16 + fl).
// Warp tile 32x64 (2 m-groups x 4 n-groups of warps).
// smem: Ah(18432) Al(18432) W(73728) = 110592 B -> 2 CTAs/SM.
template <int F>
__global__ void __launch_bounds__(256, 2)
kan_hmma(const float* __restrict__ hin, const __half* __restrict__ Wg,
         float* __restrict__ out) {
    constexpr int K = 9 * F, NCH = K / 144;
    constexpr u32 AH = 0, AL = 18432, WO = 36864;
    extern __shared__ __align__(16) char smem[];
    const u32 sbase = smem_u32(smem);

    const int tid = threadIdx.x;
    const int lane = tid & 31, warp = tid >> 5;
    const int wm = (warp & 1) * 32;              // 2 m-groups of 32 rows
    const int wn = (warp >> 1) * 64;             // 4 n-groups of 64 cols
    const int row0 = blockIdx.x * 64;

    int rowA[2], rowB[4];
    const int bitA = lane >> 4;
    const int bitB = (lane >> 3) & 1;
#pragma unroll
    for (int mi = 0; mi < 2; mi++) rowA[mi] = wm + mi * 16 + (lane & 15);
#pragma unroll
    for (int jj = 0; jj < 4; jj++) rowB[jj] = wn + jj * 16 + (lane & 7) + ((lane >> 4) << 3);

    float acc[2][8][4];
#pragma unroll
    for (int mi = 0; mi < 2; mi++)
#pragma unroll
        for (int nf = 0; nf < 8; nf++)
#pragma unroll
            for (int q = 0; q < 4; q++) acc[mi][nf][q] = 0.0f;

    for (int c = 0; c < NCH; c++) {
        __syncthreads();                          // previous chunk's MMA done
        // ---- W tile via cp.async: 256 rows x 18 uint4, swizzled dst
#pragma unroll
        for (int i = 0; i < 18; i++) {
            int u = tid + 256 * i;
            int row = u / 18, pos = u - row * 18;
            size_t gi = ((size_t)row * K + c * 144) / 8 + pos;
            cp16(sbase + WO + swz_off(row, pos), reinterpret_cast<const uint4*>(Wg) + gi);
        }
        asm volatile("cp.async.commit_group;" ::: "memory");
        // ---- produce A chunk: 64 rows x 16 features (fp16 hi/lo), k = j*16+fl
#pragma unroll
        for (int i = 0; i < 4; i++) {
            int id = tid + 256 * i;
            int fl = id & 15, row = id >> 4;      // row 0..63
            float t = hin[(size_t)(row0 + row) * F + c * 16 + fl];
            float v[9];
            v[0] = silu_f(t);
            bspline8(t, v + 1);
            const int ub = fl >> 3, bo = (fl & 7) * 2;
#pragma unroll
            for (int j = 0; j < 9; j++) {
                u32 off = swz_off(row, 2 * j + ub) + bo;
                __half hi = __float2half_rn(v[j]);
                *reinterpret_cast<__half*>(smem + AH + off) = hi;
                *reinterpret_cast<__half*>(smem + AL + off) =
                    __float2half_rn(v[j] - __half2float(hi));
            }
        }
        asm volatile("cp.async.wait_group 0;" ::: "memory");
        __syncthreads();
        // ---- 9 k16 steps: 2-term fp16 mma, warp tile 32x64
#pragma unroll
        for (int ks = 0; ks < 9; ks++) {
            u32 ah[2][4], al[2][4], b[4][4];
#pragma unroll
            for (int mi = 0; mi < 2; mi++) {
                u32 off = swz_off(rowA[mi], 2 * ks + bitA);
                ldsm_x4(ah[mi], sbase + AH + off);
                ldsm_x4(al[mi], sbase + AL + off);
            }
#pragma unroll
            for (int jj = 0; jj < 4; jj++) {
                u32 off = swz_off(rowB[jj], 2 * ks + bitB);
                ldsm_x4(b[jj], sbase + WO + off);
            }
#pragma unroll
            for (int mi = 0; mi < 2; mi++)
#pragma unroll
                for (int nf = 0; nf < 8; nf++) {
                    const u32* B = &b[nf >> 1][(nf & 1) * 2];
                    mma_f16(acc[mi][nf], ah[mi], B);
                    mma_f16(acc[mi][nf], al[mi], B);
                }
        }
    }
    // ---- epilogue: c-frag direct stores
#pragma unroll
    for (int mi = 0; mi < 2; mi++)
#pragma unroll
        for (int nf = 0; nf < 8; nf++) {
            int r0 = row0 + wm + mi * 16 + (lane >> 2);
            int cc = wn + nf * 8 + (lane & 3) * 2;
            *reinterpret_cast<float2*>(&out[(size_t)r0 * 256 + cc]) =
                make_float2(acc[mi][nf][0], acc[mi][nf][1]);
            *reinterpret_cast<float2*>(&out[(size_t)(r0 + 8) * 256 + cc]) =
                make_float2(acc[mi][nf][2], acc[mi][nf][3]);
        }
}

// ---------------- last layer: O = 1 ------------------------------------------
__global__ void kan_last(const float* __restrict__ hin,
                         const float* __restrict__ W,
                         float* __restrict__ out) {
    __shared__ float Ws[2304];
    int tid = threadIdx.x;
#pragma unroll
    for (int i = tid; i < 2304; i += 256) Ws[i] = W[i];
    __syncthreads();
    int warp = tid >> 5, lane = tid & 31;
    int n = blockIdx.x * 8 + warp;
    float sum = 0.0f;
#pragma unroll
    for (int ff = 0; ff < 8; ff++) {
        int f = ff * 32 + lane;
        float t = hin[n * 256 + f];
        float bb[8];
        bspline8(t, bb);
        float sl = silu_f(t) * Ws[f * 9];
#pragma unroll
        for (int j = 0; j < 8; j++) sl += bb[j] * Ws[f * 9 + 1 + j];
        sum += sl;
    }
#pragma unroll
    for (int off = 16; off; off >>= 1)
        sum += __shfl_xor_sync(0xffffffffu, sum, off);
    if (lane == 0) out[n] = sum;
}

// ---------------- launch ------------------------------------------------------
extern "C" void kernel_launch(void* const* d_in, const int* in_sizes, int n_in,
                              void* d_out, int out_size) {
    const float* x    = (const float*)d_in[0];
    const float* freq = (const float*)d_in[1];
    const float* bw0  = (const float*)d_in[2];
    const float* sw0  = (const float*)d_in[3];
    const float* ss0  = (const float*)d_in[4];
    const float* bw1  = (const float*)d_in[5];
    const float* sw1  = (const float*)d_in[6];
    const float* ss1  = (const float*)d_in[7];
    const float* bw2  = (const float*)d_in[8];
    const float* sw2  = (const float*)d_in[9];
    const float* ss2  = (const float*)d_in[10];
    const float* bw3  = (const float*)d_in[11];
    const float* sw3  = (const float*)d_in[12];
    const float* ss3  = (const float*)d_in[13];
    float* out = (float*)d_out;

    float *bufA, *bufB, *w3;
    __half *W0, *W1, *W2;
    cudaGetSymbolAddress((void**)&bufA, g_bufA);
    cudaGetSymbolAddress((void**)&bufB, g_bufB);
    cudaGetSymbolAddress((void**)&W0, g_W0);
    cudaGetSymbolAddress((void**)&W1, g_W1);
    cudaGetSymbolAddress((void**)&W2, g_W2);
    cudaGetSymbolAddress((void**)&w3, g_w3);

    const int SMEM = 110592;
    cudaFuncSetAttribute(kan_hmma<32>,  cudaFuncAttributeMaxDynamicSharedMemorySize, SMEM);
    cudaFuncSetAttribute(kan_hmma<256>, cudaFuncAttributeMaxDynamicSharedMemorySize, SMEM);

    // [0] all weight prep in one launch
    prep_all<<<4905, 256>>>(bw0, sw0, ss0, bw1, sw1, ss1, bw2, sw2, ss2,
                            bw3, sw3, ss3, W0, W1, W2, w3);
    // [1] encoding
    encode_kernel<<<(N_PTS * 16) / 256, 256>>>(x, freq, bufA);

    // [2] layer 0
    kan_hmma<32><<<N_PTS / 64, 256, SMEM>>>(bufA, W0, bufB);
    // [3] layer 1  (<- ncu capture slot)
    kan_hmma<256><<<N_PTS / 64, 256, SMEM>>>(bufB, W1, bufA);
    // [4] layer 2
    kan_hmma<256><<<N_PTS / 64, 256, SMEM>>>(bufA, W2, bufB);
    // [5] last layer
    kan_last<<<N_PTS / 8, 256>>>(bufB, w3, out);
}

// round 11
// speedup vs baseline: 2.4137x; 1.1310x over previous
#include <cuda_runtime.h>
#include <cuda_fp16.h>
#include <math.h>
#include <stdint.h>

#define N_PTS 32768
typedef uint32_t u32;

// ---------------- scratch (device globals; no allocations allowed) ----------
__device__ float g_bufA[N_PTS * 256];
__device__ float g_bufB[N_PTS * 256];
__device__ __align__(16) __half g_W0[256 * 288];
__device__ __align__(16) __half g_W1[256 * 2304];
__device__ __align__(16) __half g_W2[256 * 2304];
__device__ float g_w3[2304];

// ---------------- PTX helpers (compute_80-era, arch-neutral) -----------------
__device__ __forceinline__ u32 smem_u32(const void* p) {
    u32 a;
    asm("{ .reg .u64 t; cvta.to.shared.u64 t, %1; cvt.u32.u64 %0, t; }"
        : "=r"(a) : "l"(p));
    return a;
}
__device__ __forceinline__ void ldsm_x4(u32* r, u32 addr) {
    asm volatile("ldmatrix.sync.aligned.m8n8.x4.shared.b16 {%0,%1,%2,%3}, [%4];"
                 : "=r"(r[0]), "=r"(r[1]), "=r"(r[2]), "=r"(r[3]) : "r"(addr));
}
__device__ __forceinline__ void mma_f16(float* c, const u32* a, const u32* b) {
    asm volatile(
        "mma.sync.aligned.m16n8k16.row.col.f32.f16.f16.f32 "
        "{%0,%1,%2,%3}, {%4,%5,%6,%7}, {%8,%9}, {%0,%1,%2,%3};"
        : "+f"(c[0]), "+f"(c[1]), "+f"(c[2]), "+f"(c[3])
        : "r"(a[0]), "r"(a[1]), "r"(a[2]), "r"(a[3]), "r"(b[0]), "r"(b[1]));
}
__device__ __forceinline__ void cp16(u32 dst, const void* src) {
    asm volatile("cp.async.cg.shared.global [%0], [%1], 16;"
                 :: "r"(dst), "l"(src) : "memory");
}

// ---------------- closed-form cubic B-spline (uniform knots) -----------------
__device__ __forceinline__ void bspline8(float t, float* bb) {
    float u = (t + 2.2f) * 2.5f;
    float fj = floorf(u);
    int jc = (int)fj;
    float w = u - fj;
    float om = 1.0f - w;
    float w2 = w * w, w3 = w2 * w;
    float p0 = om * om * om * (1.0f / 6.0f);
    float p1 = (3.0f * w3 - 6.0f * w2 + 4.0f) * (1.0f / 6.0f);
    float p2 = (-3.0f * w3 + 3.0f * w2 + 3.0f * w + 1.0f) * (1.0f / 6.0f);
    float p3 = w3 * (1.0f / 6.0f);
#pragma unroll
    for (int i = 0; i < 8; i++) {
        int m = i - jc + 3;
        float v = (m == 0) ? p0 : (m == 1) ? p1 : (m == 2) ? p2 : (m == 3) ? p3 : 0.0f;
        bb[i] = v;
    }
}
__device__ __forceinline__ float silu_f(float v) {
    return v * (1.0f / (1.0f + __expf(-v)));
}

// ---------------- fused weight prep (single launch) --------------------------
// K layout PERMUTED per 144-chunk: k = c*144 + j*16 + fl, feature f = c*16+fl.
__device__ __forceinline__ void prep_one(const float* bw, const float* sw,
                                         const float* ss, __half* W,
                                         int F, int idx) {
    int K = 9 * F;
    if (idx >= 256 * K) return;
    int o = idx / K, k = idx - o * K;
    int c = k / 144, r = k - c * 144;
    int j = r >> 4, fl = r & 15;
    int f = c * 16 + fl;
    float v = (j == 0) ? bw[o * F + f] : sw[(o * F + f) * 8 + (j - 1)] * ss[o * F + f];
    W[idx] = __float2half_rn(v);
}
__global__ void prep_all(const float* __restrict__ bw0, const float* __restrict__ sw0, const float* __restrict__ ss0,
                         const float* __restrict__ bw1, const float* __restrict__ sw1, const float* __restrict__ ss1,
                         const float* __restrict__ bw2, const float* __restrict__ sw2, const float* __restrict__ ss2,
                         const float* __restrict__ bw3, const float* __restrict__ sw3, const float* __restrict__ ss3,
                         __half* __restrict__ W0, __half* __restrict__ W1, __half* __restrict__ W2,
                         float* __restrict__ w3) {
    int b = blockIdx.x, t = threadIdx.x;
    if (b < 288) {
        prep_one(bw0, sw0, ss0, W0, 32, b * 256 + t);
    } else if (b < 2592) {
        prep_one(bw1, sw1, ss1, W1, 256, (b - 288) * 256 + t);
    } else if (b < 4896) {
        prep_one(bw2, sw2, ss2, W2, 256, (b - 2592) * 256 + t);
    } else {
        int k = (b - 4896) * 256 + t;
        if (k < 2304) {
            int f = k / 9, j = k - f * 9;
            w3[k] = (j == 0) ? bw3[f] : sw3[f * 8 + (j - 1)] * ss3[f];
        }
    }
}

// ---------------- positional encoding ---------------------------------------
__global__ void encode_kernel(const float* __restrict__ x,
                              const float* __restrict__ freq,
                              float* __restrict__ h0) {
    int idx = blockIdx.x * blockDim.x + threadIdx.x;
    if (idx >= N_PTS * 16) return;
    int n = idx >> 4, j = idx & 15;
    float enc = x[n] * freq[j];
    double ed = (double)enc;
    double q = rint(ed * 0.15915494309189535);
    double rd = fma(-q, 6.283185307179586, ed);
    float r = (float)rd;
    float s, c;
    __sincosf(r, &s, &c);
    h0[n * 32 + j] = s;
    h0[n * 32 + 16 + j] = c;
}

// ---------------- smem swizzle: row stride 288 B (18 x 16B units) ------------
__device__ __forceinline__ u32 swz_off(int row, int u) {
    if (u < 16) return (u32)(row * 288 + ((u * 16) ^ ((row & 7) * 16)));
    return (u32)(row * 288 + 256 + (((u ^ row) & 1) * 16));
}

// ---------------- fused HMMA KAN layer ---------------------------------------
// Single fp16 term: a_fp16 * w_fp16 (error budget verified in R10/R11).
// CTA tile: 64 rows x 256 cols (FULL N). K chunks of 144 (k = j*16 + fl).
// Warp tile 32x64 (2 m-groups x 4 n-groups of warps).
// smem: A(18432) W(73728) = 92160 B -> 2 CTAs/SM.
template <int F>
__global__ void __launch_bounds__(256, 2)
kan_hmma(const float* __restrict__ hin, const __half* __restrict__ Wg,
         float* __restrict__ out) {
    constexpr int K = 9 * F, NCH = K / 144;
    constexpr u32 AH = 0, WO = 18432;
    extern __shared__ __align__(16) char smem[];
    const u32 sbase = smem_u32(smem);

    const int tid = threadIdx.x;
    const int lane = tid & 31, warp = tid >> 5;
    const int wm = (warp & 1) * 32;              // 2 m-groups of 32 rows
    const int wn = (warp >> 1) * 64;             // 4 n-groups of 64 cols
    const int row0 = blockIdx.x * 64;

    int rowA[2], rowB[4];
    const int bitA = lane >> 4;
    const int bitB = (lane >> 3) & 1;
#pragma unroll
    for (int mi = 0; mi < 2; mi++) rowA[mi] = wm + mi * 16 + (lane & 15);
#pragma unroll
    for (int jj = 0; jj < 4; jj++) rowB[jj] = wn + jj * 16 + (lane & 7) + ((lane >> 4) << 3);

    float acc[2][8][4];
#pragma unroll
    for (int mi = 0; mi < 2; mi++)
#pragma unroll
        for (int nf = 0; nf < 8; nf++)
#pragma unroll
            for (int q = 0; q < 4; q++) acc[mi][nf][q] = 0.0f;

    for (int c = 0; c < NCH; c++) {
        __syncthreads();                          // previous chunk's MMA done
        // ---- W tile via cp.async: 256 rows x 18 uint4, swizzled dst
#pragma unroll
        for (int i = 0; i < 18; i++) {
            int u = tid + 256 * i;
            int row = u / 18, pos = u - row * 18;
            size_t gi = ((size_t)row * K + c * 144) / 8 + pos;
            cp16(sbase + WO + swz_off(row, pos), reinterpret_cast<const uint4*>(Wg) + gi);
        }
        asm volatile("cp.async.commit_group;" ::: "memory");
        // ---- produce A chunk: 64 rows x 16 features (fp16), k = j*16+fl
#pragma unroll
        for (int i = 0; i < 4; i++) {
            int id = tid + 256 * i;
            int fl = id & 15, row = id >> 4;      // row 0..63
            float t = hin[(size_t)(row0 + row) * F + c * 16 + fl];
            float v[9];
            v[0] = silu_f(t);
            bspline8(t, v + 1);
            const int ub = fl >> 3, bo = (fl & 7) * 2;
#pragma unroll
            for (int j = 0; j < 9; j++) {
                u32 off = swz_off(row, 2 * j + ub) + bo;
                *reinterpret_cast<__half*>(smem + AH + off) = __float2half_rn(v[j]);
            }
        }
        asm volatile("cp.async.wait_group 0;" ::: "memory");
        __syncthreads();
        // ---- 9 k16 steps: fp16 mma, warp tile 32x64
#pragma unroll
        for (int ks = 0; ks < 9; ks++) {
            u32 ah[2][4], b[4][4];
#pragma unroll
            for (int mi = 0; mi < 2; mi++)
                ldsm_x4(ah[mi], sbase + AH + swz_off(rowA[mi], 2 * ks + bitA));
#pragma unroll
            for (int jj = 0; jj < 4; jj++)
                ldsm_x4(b[jj], sbase + WO + swz_off(rowB[jj], 2 * ks + bitB));
#pragma unroll
            for (int mi = 0; mi < 2; mi++)
#pragma unroll
                for (int nf = 0; nf < 8; nf++)
                    mma_f16(acc[mi][nf], ah[mi], &b[nf >> 1][(nf & 1) * 2]);
        }
    }
    // ---- epilogue: c-frag direct stores
#pragma unroll
    for (int mi = 0; mi < 2; mi++)
#pragma unroll
        for (int nf = 0; nf < 8; nf++) {
            int r0 = row0 + wm + mi * 16 + (lane >> 2);
            int cc = wn + nf * 8 + (lane & 3) * 2;
            *reinterpret_cast<float2*>(&out[(size_t)r0 * 256 + cc]) =
                make_float2(acc[mi][nf][0], acc[mi][nf][1]);
            *reinterpret_cast<float2*>(&out[(size_t)(r0 + 8) * 256 + cc]) =
                make_float2(acc[mi][nf][2], acc[mi][nf][3]);
        }
}

// ---------------- last layer: O = 1 ------------------------------------------
__global__ void kan_last(const float* __restrict__ hin,
                         const float* __restrict__ W,
                         float* __restrict__ out) {
    __shared__ float Ws[2304];
    int tid = threadIdx.x;
#pragma unroll
    for (int i = tid; i < 2304; i += 256) Ws[i] = W[i];
    __syncthreads();
    int warp = tid >> 5, lane = tid & 31;
    int n = blockIdx.x * 8 + warp;
    float sum = 0.0f;
#pragma unroll
    for (int ff = 0; ff < 8; ff++) {
        int f = ff * 32 + lane;
        float t = hin[n * 256 + f];
        float bb[8];
        bspline8(t, bb);
        float sl = silu_f(t) * Ws[f * 9];
#pragma unroll
        for (int j = 0; j < 8; j++) sl += bb[j] * Ws[f * 9 + 1 + j];
        sum += sl;
    }
#pragma unroll
    for (int off = 16; off; off >>= 1)
        sum += __shfl_xor_sync(0xffffffffu, sum, off);
    if (lane == 0) out[n] = sum;
}

// ---------------- launch ------------------------------------------------------
extern "C" void kernel_launch(void* const* d_in, const int* in_sizes, int n_in,
                              void* d_out, int out_size) {
    const float* x    = (const float*)d_in[0];
    const float* freq = (const float*)d_in[1];
    const float* bw0  = (const float*)d_in[2];
    const float* sw0  = (const float*)d_in[3];
    const float* ss0  = (const float*)d_in[4];
    const float* bw1  = (const float*)d_in[5];
    const float* sw1  = (const float*)d_in[6];
    const float* ss1  = (const float*)d_in[7];
    const float* bw2  = (const float*)d_in[8];
    const float* sw2  = (const float*)d_in[9];
    const float* ss2  = (const float*)d_in[10];
    const float* bw3  = (const float*)d_in[11];
    const float* sw3  = (const float*)d_in[12];
    const float* ss3  = (const float*)d_in[13];
    float* out = (float*)d_out;

    float *bufA, *bufB, *w3;
    __half *W0, *W1, *W2;
    cudaGetSymbolAddress((void**)&bufA, g_bufA);
    cudaGetSymbolAddress((void**)&bufB, g_bufB);
    cudaGetSymbolAddress((void**)&W0, g_W0);
    cudaGetSymbolAddress((void**)&W1, g_W1);
    cudaGetSymbolAddress((void**)&W2, g_W2);
    cudaGetSymbolAddress((void**)&w3, g_w3);

    const int SMEM = 92160;
    cudaFuncSetAttribute(kan_hmma<32>,  cudaFuncAttributeMaxDynamicSharedMemorySize, SMEM);
    cudaFuncSetAttribute(kan_hmma<256>, cudaFuncAttributeMaxDynamicSharedMemorySize, SMEM);

    // [0] all weight prep in one launch
    prep_all<<<4905, 256>>>(bw0, sw0, ss0, bw1, sw1, ss1, bw2, sw2, ss2,
                            bw3, sw3, ss3, W0, W1, W2, w3);
    // [1] encoding
    encode_kernel<<<(N_PTS * 16) / 256, 256>>>(x, freq, bufA);

    // [2] layer 0
    kan_hmma<32><<<N_PTS / 64, 256, SMEM>>>(bufA, W0, bufB);
    // [3] layer 1  (<- ncu capture slot)
    kan_hmma<256><<<N_PTS / 64, 256, SMEM>>>(bufB, W1, bufA);
    // [4] layer 2
    kan_hmma<256><<<N_PTS / 64, 256, SMEM>>>(bufA, W2, bufB);
    // [5] last layer
    kan_last<<<N_PTS / 8, 256>>>(bufB, w3, out);
}

// round 12
// speedup vs baseline: 2.4577x; 1.0182x over previous
#include <cuda_runtime.h>
#include <cuda_fp16.h>
#include <math.h>
#include <stdint.h>

#define N_PTS 32768
typedef uint32_t u32;

// ---------------- scratch (device globals; no allocations allowed) ----------
__device__ float g_bufA[N_PTS * 256];
__device__ float g_bufB[N_PTS * 256];
__device__ __align__(16) __half g_W0[256 * 288];
__device__ __align__(16) __half g_W1[256 * 2304];
__device__ __align__(16) __half g_W2[256 * 2304];
__device__ float g_w3[2304];

// ---------------- PTX helpers (compute_80-era, arch-neutral) -----------------
__device__ __forceinline__ u32 smem_u32(const void* p) {
    u32 a;
    asm("{ .reg .u64 t; cvta.to.shared.u64 t, %1; cvt.u32.u64 %0, t; }"
        : "=r"(a) : "l"(p));
    return a;
}
__device__ __forceinline__ void ldsm_x4(u32* r, u32 addr) {
    asm volatile("ldmatrix.sync.aligned.m8n8.x4.shared.b16 {%0,%1,%2,%3}, [%4];"
                 : "=r"(r[0]), "=r"(r[1]), "=r"(r[2]), "=r"(r[3]) : "r"(addr));
}
__device__ __forceinline__ void mma_f16(float* c, const u32* a, const u32* b) {
    asm volatile(
        "mma.sync.aligned.m16n8k16.row.col.f32.f16.f16.f32 "
        "{%0,%1,%2,%3}, {%4,%5,%6,%7}, {%8,%9}, {%0,%1,%2,%3};"
        : "+f"(c[0]), "+f"(c[1]), "+f"(c[2]), "+f"(c[3])
        : "r"(a[0]), "r"(a[1]), "r"(a[2]), "r"(a[3]), "r"(b[0]), "r"(b[1]));
}
__device__ __forceinline__ void cp16(u32 dst, const void* src) {
    asm volatile("cp.async.cg.shared.global [%0], [%1], 16;"
                 :: "r"(dst), "l"(src) : "memory");
}

// ---------------- closed-form cubic B-spline (uniform knots) -----------------
__device__ __forceinline__ void bspline8(float t, float* bb) {
    float u = (t + 2.2f) * 2.5f;
    float fj = floorf(u);
    int jc = (int)fj;
    float w = u - fj;
    float om = 1.0f - w;
    float w2 = w * w, w3 = w2 * w;
    float p0 = om * om * om * (1.0f / 6.0f);
    float p1 = (3.0f * w3 - 6.0f * w2 + 4.0f) * (1.0f / 6.0f);
    float p2 = (-3.0f * w3 + 3.0f * w2 + 3.0f * w + 1.0f) * (1.0f / 6.0f);
    float p3 = w3 * (1.0f / 6.0f);
#pragma unroll
    for (int i = 0; i < 8; i++) {
        int m = i - jc + 3;
        float v = (m == 0) ? p0 : (m == 1) ? p1 : (m == 2) ? p2 : (m == 3) ? p3 : 0.0f;
        bb[i] = v;
    }
}
__device__ __forceinline__ float silu_f(float v) {
    return v * (1.0f / (1.0f + __expf(-v)));
}

// ---------------- fused weight prep (single launch) --------------------------
// K layout PERMUTED per 144-chunk: k = c*144 + j*16 + fl, feature f = c*16+fl.
__device__ __forceinline__ void prep_one(const float* bw, const float* sw,
                                         const float* ss, __half* W,
                                         int F, int idx) {
    int K = 9 * F;
    if (idx >= 256 * K) return;
    int o = idx / K, k = idx - o * K;
    int c = k / 144, r = k - c * 144;
    int j = r >> 4, fl = r & 15;
    int f = c * 16 + fl;
    float v = (j == 0) ? bw[o * F + f] : sw[(o * F + f) * 8 + (j - 1)] * ss[o * F + f];
    W[idx] = __float2half_rn(v);
}
__global__ void prep_all(const float* __restrict__ bw0, const float* __restrict__ sw0, const float* __restrict__ ss0,
                         const float* __restrict__ bw1, const float* __restrict__ sw1, const float* __restrict__ ss1,
                         const float* __restrict__ bw2, const float* __restrict__ sw2, const float* __restrict__ ss2,
                         const float* __restrict__ bw3, const float* __restrict__ sw3, const float* __restrict__ ss3,
                         __half* __restrict__ W0, __half* __restrict__ W1, __half* __restrict__ W2,
                         float* __restrict__ w3) {
    int b = blockIdx.x, t = threadIdx.x;
    if (b < 288) {
        prep_one(bw0, sw0, ss0, W0, 32, b * 256 + t);
    } else if (b < 2592) {
        prep_one(bw1, sw1, ss1, W1, 256, (b - 288) * 256 + t);
    } else if (b < 4896) {
        prep_one(bw2, sw2, ss2, W2, 256, (b - 2592) * 256 + t);
    } else {
        int k = (b - 4896) * 256 + t;
        if (k < 2304) {
            int f = k / 9, j = k - f * 9;
            w3[k] = (j == 0) ? bw3[f] : sw3[f * 8 + (j - 1)] * ss3[f];
        }
    }
}

// ---------------- positional encoding ---------------------------------------
__global__ void encode_kernel(const float* __restrict__ x,
                              const float* __restrict__ freq,
                              float* __restrict__ h0) {
    int idx = blockIdx.x * blockDim.x + threadIdx.x;
    if (idx >= N_PTS * 16) return;
    int n = idx >> 4, j = idx & 15;
    float enc = x[n] * freq[j];
    double ed = (double)enc;
    double q = rint(ed * 0.15915494309189535);
    double rd = fma(-q, 6.283185307179586, ed);
    float r = (float)rd;
    float s, c;
    __sincosf(r, &s, &c);
    h0[n * 32 + j] = s;
    h0[n * 32 + 16 + j] = c;
}

// ---------------- smem swizzle: row stride 288 B (18 x 16B units) ------------
__device__ __forceinline__ u32 swz_off(int row, int u) {
    if (u < 16) return (u32)(row * 288 + ((u * 16) ^ ((row & 7) * 16)));
    return (u32)(row * 288 + 256 + (((u ^ row) & 1) * 16));
}

// ---------------- fused HMMA KAN layer, 512 threads, 2-stage pipeline --------
// Single fp16 term. CTA tile: 64 rows x 256 cols. K chunks of 144 (k=j*16+fl).
// 16 warps: 2 m-groups x 8 n-groups, warp tile 32x32.
// Stage (92160 B): A@0 W@18432. Two stages = 184320 B -> 1 CTA/SM, 4 w/SMSP.
template <int F>
__global__ void __launch_bounds__(512, 1)
kan_hmma(const float* __restrict__ hin, const __half* __restrict__ Wg,
         float* __restrict__ out) {
    constexpr int K = 9 * F, NCH = K / 144;
    constexpr u32 STG = 92160;
    constexpr u32 AO = 0, WO = 18432;
    extern __shared__ __align__(16) char smem[];
    const u32 sbase = smem_u32(smem);

    const int tid = threadIdx.x;
    const int lane = tid & 31, warp = tid >> 5;
    const int wm = (warp & 1) * 32;              // 2 m-groups of 32 rows
    const int wn = (warp >> 1) * 32;             // 8 n-groups of 32 cols
    const int row0 = blockIdx.x * 64;

    int rowA[2], rowB[2];
    const int bitA = lane >> 4;
    const int bitB = (lane >> 3) & 1;
#pragma unroll
    for (int mi = 0; mi < 2; mi++) rowA[mi] = wm + mi * 16 + (lane & 15);
#pragma unroll
    for (int jj = 0; jj < 2; jj++) rowB[jj] = wn + jj * 16 + (lane & 7) + ((lane >> 4) << 3);

    float acc[2][4][4];
#pragma unroll
    for (int mi = 0; mi < 2; mi++)
#pragma unroll
        for (int nf = 0; nf < 4; nf++)
#pragma unroll
            for (int q = 0; q < 4; q++) acc[mi][nf][q] = 0.0f;

    // ---- helpers
    auto issueW = [&](int c, u32 sb) {
#pragma unroll
        for (int i = 0; i < 9; i++) {
            int u = tid + 512 * i;
            int row = u / 18, pos = u - row * 18;
            size_t gi = ((size_t)row * K + c * 144) / 8 + pos;
            cp16(sbase + sb + WO + swz_off(row, pos),
                 reinterpret_cast<const uint4*>(Wg) + gi);
        }
    };
    auto produceA = [&](int c, u32 sb, int half) {
        int id = tid + 512 * half;                // 1024 items, 2 halves
        int fl = id & 15, row = id >> 4;          // row 0..63
        float t = hin[(size_t)(row0 + row) * F + c * 16 + fl];
        float v[9];
        v[0] = silu_f(t);
        bspline8(t, v + 1);
        const int ub = fl >> 3, bo = (fl & 7) * 2;
#pragma unroll
        for (int j = 0; j < 9; j++) {
            u32 off = swz_off(row, 2 * j + ub) + bo;
            *reinterpret_cast<__half*>(smem + sb + AO + off) = __float2half_rn(v[j]);
        }
    };

    // ---- prologue: fill stage 0
    issueW(0, 0);
    asm volatile("cp.async.commit_group;" ::: "memory");
    produceA(0, 0, 0);
    produceA(0, 0, 1);

    for (int c = 0; c < NCH; c++) {
        const u32 sb = (u32)(c & 1) * STG;
        const u32 sbn = (u32)((c + 1) & 1) * STG;
        asm volatile("cp.async.wait_group 0;" ::: "memory");
        __syncthreads();                          // W(c),A(c) ready; stage sbn free
        const bool more = (c + 1 < NCH);
        if (more) {
            issueW(c + 1, sbn);
            asm volatile("cp.async.commit_group;" ::: "memory");
        }
#pragma unroll
        for (int ks = 0; ks < 9; ks++) {
            u32 ah[2][4], b[2][4];
#pragma unroll
            for (int mi = 0; mi < 2; mi++)
                ldsm_x4(ah[mi], sbase + sb + AO + swz_off(rowA[mi], 2 * ks + bitA));
#pragma unroll
            for (int jj = 0; jj < 2; jj++)
                ldsm_x4(b[jj], sbase + sb + WO + swz_off(rowB[jj], 2 * ks + bitB));
#pragma unroll
            for (int mi = 0; mi < 2; mi++)
#pragma unroll
                for (int nf = 0; nf < 4; nf++)
                    mma_f16(acc[mi][nf], ah[mi], &b[nf >> 1][(nf & 1) * 2]);
            // interleave next-chunk A production under the MMA window
            if (more && ks == 0) produceA(c + 1, sbn, 0);
            if (more && ks == 4) produceA(c + 1, sbn, 1);
        }
    }
    // ---- epilogue: c-frag direct stores
#pragma unroll
    for (int mi = 0; mi < 2; mi++)
#pragma unroll
        for (int nf = 0; nf < 4; nf++) {
            int r0 = row0 + wm + mi * 16 + (lane >> 2);
            int cc = wn + nf * 8 + (lane & 3) * 2;
            *reinterpret_cast<float2*>(&out[(size_t)r0 * 256 + cc]) =
                make_float2(acc[mi][nf][0], acc[mi][nf][1]);
            *reinterpret_cast<float2*>(&out[(size_t)(r0 + 8) * 256 + cc]) =
                make_float2(acc[mi][nf][2], acc[mi][nf][3]);
        }
}

// ---------------- last layer: O = 1 ------------------------------------------
__global__ void kan_last(const float* __restrict__ hin,
                         const float* __restrict__ W,
                         float* __restrict__ out) {
    __shared__ float Ws[2304];
    int tid = threadIdx.x;
#pragma unroll
    for (int i = tid; i < 2304; i += 256) Ws[i] = W[i];
    __syncthreads();
    int warp = tid >> 5, lane = tid & 31;
    int n = blockIdx.x * 8 + warp;
    float sum = 0.0f;
#pragma unroll
    for (int ff = 0; ff < 8; ff++) {
        int f = ff * 32 + lane;
        float t = hin[n * 256 + f];
        float bb[8];
        bspline8(t, bb);
        float sl = silu_f(t) * Ws[f * 9];
#pragma unroll
        for (int j = 0; j < 8; j++) sl += bb[j] * Ws[f * 9 + 1 + j];
        sum += sl;
    }
#pragma unroll
    for (int off = 16; off; off >>= 1)
        sum += __shfl_xor_sync(0xffffffffu, sum, off);
    if (lane == 0) out[n] = sum;
}

// ---------------- launch ------------------------------------------------------
extern "C" void kernel_launch(void* const* d_in, const int* in_sizes, int n_in,
                              void* d_out, int out_size) {
    const float* x    = (const float*)d_in[0];
    const float* freq = (const float*)d_in[1];
    const float* bw0  = (const float*)d_in[2];
    const float* sw0  = (const float*)d_in[3];
    const float* ss0  = (const float*)d_in[4];
    const float* bw1  = (const float*)d_in[5];
    const float* sw1  = (const float*)d_in[6];
    const float* ss1  = (const float*)d_in[7];
    const float* bw2  = (const float*)d_in[8];
    const float* sw2  = (const float*)d_in[9];
    const float* ss2  = (const float*)d_in[10];
    const float* bw3  = (const float*)d_in[11];
    const float* sw3  = (const float*)d_in[12];
    const float* ss3  = (const float*)d_in[13];
    float* out = (float*)d_out;

    float *bufA, *bufB, *w3;
    __half *W0, *W1, *W2;
    cudaGetSymbolAddress((void**)&bufA, g_bufA);
    cudaGetSymbolAddress((void**)&bufB, g_bufB);
    cudaGetSymbolAddress((void**)&W0, g_W0);
    cudaGetSymbolAddress((void**)&W1, g_W1);
    cudaGetSymbolAddress((void**)&W2, g_W2);
    cudaGetSymbolAddress((void**)&w3, g_w3);

    const int SMEM = 184320;
    cudaFuncSetAttribute(kan_hmma<32>,  cudaFuncAttributeMaxDynamicSharedMemorySize, SMEM);
    cudaFuncSetAttribute(kan_hmma<256>, cudaFuncAttributeMaxDynamicSharedMemorySize, SMEM);

    // [0] all weight prep in one launch
    prep_all<<<4905, 256>>>(bw0, sw0, ss0, bw1, sw1, ss1, bw2, sw2, ss2,
                            bw3, sw3, ss3, W0, W1, W2, w3);
    // [1] encoding
    encode_kernel<<<(N_PTS * 16) / 256, 256>>>(x, freq, bufA);

    // [2] layer 0
    kan_hmma<32><<<N_PTS / 64, 512, SMEM>>>(bufA, W0, bufB);
    // [3] layer 1  (<- ncu capture slot)
    kan_hmma<256><<<N_PTS / 64, 512, SMEM>>>(bufB, W1, bufA);
    // [4] layer 2
    kan_hmma<256><<<N_PTS / 64, 512, SMEM>>>(bufA, W2, bufB);
    // [5] last layer
    kan_last<<<N_PTS / 8, 256>>>(bufB, w3, out);
}

// round 14
// speedup vs baseline: 2.5133x; 1.0226x over previous
#include <cuda_runtime.h>
#include <cuda_fp16.h>
#include <math.h>
#include <stdint.h>

#define N_PTS 32768
typedef uint32_t u32;

// ---------------- scratch (device globals; no allocations allowed) ----------
__device__ float g_bufA[N_PTS * 256];
__device__ float g_bufB[N_PTS * 256];
__device__ __align__(16) __half g_W0[256 * 288];
__device__ __align__(16) __half g_W1[256 * 2304];
__device__ __align__(16) __half g_W2[256 * 2304];
__device__ float g_w3[2304];

// ---------------- PTX helpers (compute_80-era, arch-neutral) -----------------
__device__ __forceinline__ u32 smem_u32(const void* p) {
    u32 a;
    asm("{ .reg .u64 t; cvta.to.shared.u64 t, %1; cvt.u32.u64 %0, t; }"
        : "=r"(a) : "l"(p));
    return a;
}
__device__ __forceinline__ void ldsm_x4(u32* r, u32 addr) {
    asm volatile("ldmatrix.sync.aligned.m8n8.x4.shared.b16 {%0,%1,%2,%3}, [%4];"
                 : "=r"(r[0]), "=r"(r[1]), "=r"(r[2]), "=r"(r[3]) : "r"(addr));
}
__device__ __forceinline__ void mma_f16(float* c, const u32* a, const u32* b) {
    asm volatile(
        "mma.sync.aligned.m16n8k16.row.col.f32.f16.f16.f32 "
        "{%0,%1,%2,%3}, {%4,%5,%6,%7}, {%8,%9}, {%0,%1,%2,%3};"
        : "+f"(c[0]), "+f"(c[1]), "+f"(c[2]), "+f"(c[3])
        : "r"(a[0]), "r"(a[1]), "r"(a[2]), "r"(a[3]), "r"(b[0]), "r"(b[1]));
}
__device__ __forceinline__ void cp16(u32 dst, const void* src) {
    asm volatile("cp.async.cg.shared.global [%0], [%1], 16;"
                 :: "r"(dst), "l"(src) : "memory");
}

// ---------------- closed-form cubic B-spline (uniform knots) -----------------
__device__ __forceinline__ void bspline8(float t, float* bb) {
    float u = (t + 2.2f) * 2.5f;
    float fj = floorf(u);
    int jc = (int)fj;
    float w = u - fj;
    float om = 1.0f - w;
    float w2 = w * w, w3 = w2 * w;
    float p0 = om * om * om * (1.0f / 6.0f);
    float p1 = (3.0f * w3 - 6.0f * w2 + 4.0f) * (1.0f / 6.0f);
    float p2 = (-3.0f * w3 + 3.0f * w2 + 3.0f * w + 1.0f) * (1.0f / 6.0f);
    float p3 = w3 * (1.0f / 6.0f);
#pragma unroll
    for (int i = 0; i < 8; i++) {
        int m = i - jc + 3;
        float v = (m == 0) ? p0 : (m == 1) ? p1 : (m == 2) ? p2 : (m == 3) ? p3 : 0.0f;
        bb[i] = v;
    }
}
__device__ __forceinline__ float silu_f(float v) {
    return v * (1.0f / (1.0f + __expf(-v)));
}

// ---------------- fused weight prep (single launch) --------------------------
// K layout PERMUTED per 144-chunk: k = c*144 + j*16 + fl, feature f = c*16+fl.
__device__ __forceinline__ void prep_one(const float* bw, const float* sw,
                                         const float* ss, __half* W,
                                         int F, int idx) {
    int K = 9 * F;
    if (idx >= 256 * K) return;
    int o = idx / K, k = idx - o * K;
    int c = k / 144, r = k - c * 144;
    int j = r >> 4, fl = r & 15;
    int f = c * 16 + fl;
    float v = (j == 0) ? bw[o * F + f] : sw[(o * F + f) * 8 + (j - 1)] * ss[o * F + f];
    W[idx] = __float2half_rn(v);
}
__global__ void prep_all(const float* __restrict__ bw0, const float* __restrict__ sw0, const float* __restrict__ ss0,
                         const float* __restrict__ bw1, const float* __restrict__ sw1, const float* __restrict__ ss1,
                         const float* __restrict__ bw2, const float* __restrict__ sw2, const float* __restrict__ ss2,
                         const float* __restrict__ bw3, const float* __restrict__ sw3, const float* __restrict__ ss3,
                         __half* __restrict__ W0, __half* __restrict__ W1, __half* __restrict__ W2,
                         float* __restrict__ w3) {
    int b = blockIdx.x, t = threadIdx.x;
    if (b < 288) {
        prep_one(bw0, sw0, ss0, W0, 32, b * 256 + t);
    } else if (b < 2592) {
        prep_one(bw1, sw1, ss1, W1, 256, (b - 288) * 256 + t);
    } else if (b < 4896) {
        prep_one(bw2, sw2, ss2, W2, 256, (b - 2592) * 256 + t);
    } else {
        int k = (b - 4896) * 256 + t;
        if (k < 2304) {
            int f = k / 9, j = k - f * 9;
            w3[k] = (j == 0) ? bw3[f] : sw3[f * 8 + (j - 1)] * ss3[f];
        }
    }
}

// ---------------- positional encoding ---------------------------------------
__global__ void encode_kernel(const float* __restrict__ x,
                              const float* __restrict__ freq,
                              float* __restrict__ h0) {
    int idx = blockIdx.x * blockDim.x + threadIdx.x;
    if (idx >= N_PTS * 16) return;
    int n = idx >> 4, j = idx & 15;
    float enc = x[n] * freq[j];
    double ed = (double)enc;
    double q = rint(ed * 0.15915494309189535);
    double rd = fma(-q, 6.283185307179586, ed);
    float r = (float)rd;
    float s, c;
    __sincosf(r, &s, &c);
    h0[n * 32 + j] = s;
    h0[n * 32 + 16 + j] = c;
}

// ---------------- smem swizzle: row stride 288 B (18 x 16B units) ------------
__device__ __forceinline__ u32 swz_off(int row, int u) {
    if (u < 16) return (u32)(row * 288 + ((u * 16) ^ ((row & 7) * 16)));
    return (u32)(row * 288 + 256 + (((u ^ row) & 1) * 16));
}

// ---------------- fused HMMA KAN layer, 512 threads, 2-stage pipeline --------
// Single fp16 term. CTA tile: 64 rows x 256 cols. K chunks of 144 (k=j*16+fl).
// 16 warps: 2 m-groups x 8 n-groups, warp tile 32x32.
// Activation LDGs for chunk c+1 are issued at the top of chunk c's MMA loop
// (long-scoreboard covered by the whole loop); spline+STS consume them late.
// Stage (92160 B): A@0 W@18432. Two stages = 184320 B -> 1 CTA/SM, 4 w/SMSP.
template <int F>
__global__ void __launch_bounds__(512, 1)
kan_hmma(const float* __restrict__ hin, const __half* __restrict__ Wg,
         float* __restrict__ out) {
    constexpr int K = 9 * F, NCH = K / 144;
    constexpr u32 STG = 92160;
    constexpr u32 AO = 0, WO = 18432;
    extern __shared__ __align__(16) char smem[];
    const u32 sbase = smem_u32(smem);

    const int tid = threadIdx.x;
    const int lane = tid & 31, warp = tid >> 5;
    const int wm = (warp & 1) * 32;              // 2 m-groups of 32 rows
    const int wn = (warp >> 1) * 32;             // 8 n-groups of 32 cols
    const int row0 = blockIdx.x * 64;

    int rowA[2], rowB[2];
    const int bitA = lane >> 4;
    const int bitB = (lane >> 3) & 1;
#pragma unroll
    for (int mi = 0; mi < 2; mi++) rowA[mi] = wm + mi * 16 + (lane & 15);
#pragma unroll
    for (int jj = 0; jj < 2; jj++) rowB[jj] = wn + jj * 16 + (lane & 7) + ((lane >> 4) << 3);

    // item->(row, feature) decode for the two A items this thread owns
    const int fl0 = tid & 15,          rA0 = tid >> 4;          // item 0
    const int fl1 = (tid + 512) & 15,  rA1 = (tid + 512) >> 4;  // item 1

    float acc[2][4][4];
#pragma unroll
    for (int mi = 0; mi < 2; mi++)
#pragma unroll
        for (int nf = 0; nf < 4; nf++)
#pragma unroll
            for (int q = 0; q < 4; q++) acc[mi][nf][q] = 0.0f;

    // ---- helpers
    auto issueW = [&](int c, u32 sb) {
#pragma unroll
        for (int i = 0; i < 9; i++) {
            int u = tid + 512 * i;
            int row = u / 18, pos = u - row * 18;
            size_t gi = ((size_t)row * K + c * 144) / 8 + pos;
            cp16(sbase + sb + WO + swz_off(row, pos),
                 reinterpret_cast<const uint4*>(Wg) + gi);
        }
    };
    auto storeA = [&](float t, int fl, int row, u32 sb) {
        float v[9];
        v[0] = silu_f(t);
        bspline8(t, v + 1);
        const int ub = fl >> 3, bo = (fl & 7) * 2;
#pragma unroll
        for (int j = 0; j < 9; j++) {
            u32 off = swz_off(row, 2 * j + ub) + bo;
            *reinterpret_cast<__half*>(smem + sb + AO + off) = __float2half_rn(v[j]);
        }
    };

    // ---- prologue: fill stage 0
    {
        float p0 = hin[(size_t)(row0 + rA0) * F + fl0];
        float p1 = hin[(size_t)(row0 + rA1) * F + fl1];
        issueW(0, 0);
        asm volatile("cp.async.commit_group;" ::: "memory");
        storeA(p0, fl0, rA0, 0);
        storeA(p1, fl1, rA1, 0);
    }

    for (int c = 0; c < NCH; c++) {
        const u32 sb = (u32)(c & 1) * STG;
        const u32 sbn = (u32)((c + 1) & 1) * STG;
        asm volatile("cp.async.wait_group 0;" ::: "memory");
        __syncthreads();                          // W(c),A(c) ready; stage sbn free
        const bool more = (c + 1 < NCH);
        float t0 = 0.0f, t1 = 0.0f;
        if (more) {
            // prefetch activations for chunk c+1 FIRST (in flight under mma loop)
            t0 = hin[(size_t)(row0 + rA0) * F + (c + 1) * 16 + fl0];
            t1 = hin[(size_t)(row0 + rA1) * F + (c + 1) * 16 + fl1];
            issueW(c + 1, sbn);
            asm volatile("cp.async.commit_group;" ::: "memory");
        }
#pragma unroll
        for (int ks = 0; ks < 9; ks++) {
            u32 ah[2][4], b[2][4];
#pragma unroll
            for (int mi = 0; mi < 2; mi++)
                ldsm_x4(ah[mi], sbase + sb + AO + swz_off(rowA[mi], 2 * ks + bitA));
#pragma unroll
            for (int jj = 0; jj < 2; jj++)
                ldsm_x4(b[jj], sbase + sb + WO + swz_off(rowB[jj], 2 * ks + bitB));
#pragma unroll
            for (int mi = 0; mi < 2; mi++)
#pragma unroll
                for (int nf = 0; nf < 4; nf++)
                    mma_f16(acc[mi][nf], ah[mi], &b[nf >> 1][(nf & 1) * 2]);
            // consume prefetched activations late (loads have landed by now)
            if (more && ks == 6) storeA(t0, fl0, rA0, sbn);
            if (more && ks == 8) storeA(t1, fl1, rA1, sbn);
        }
    }
    // ---- epilogue: c-frag direct stores
#pragma unroll
    for (int mi = 0; mi < 2; mi++)
#pragma unroll
        for (int nf = 0; nf < 4; nf++) {
            int r0 = row0 + wm + mi * 16 + (lane >> 2);
            int cc = wn + nf * 8 + (lane & 3) * 2;
            *reinterpret_cast<float2*>(&out[(size_t)r0 * 256 + cc]) =
                make_float2(acc[mi][nf][0], acc[mi][nf][1]);
            *reinterpret_cast<float2*>(&out[(size_t)(r0 + 8) * 256 + cc]) =
                make_float2(acc[mi][nf][2], acc[mi][nf][3]);
        }
}

// ---------------- last layer: O = 1 ------------------------------------------
__global__ void kan_last(const float* __restrict__ hin,
                         const float* __restrict__ W,
                         float* __restrict__ out) {
    __shared__ float Ws[2304];
    int tid = threadIdx.x;
#pragma unroll
    for (int i = tid; i < 2304; i += 256) Ws[i] = W[i];
    __syncthreads();
    int warp = tid >> 5, lane = tid & 31;
    int n = blockIdx.x * 8 + warp;
    float sum = 0.0f;
#pragma unroll
    for (int ff = 0; ff < 8; ff++) {
        int f = ff * 32 + lane;
        float t = hin[n * 256 + f];
        float bb[8];
        bspline8(t, bb);
        float sl = silu_f(t) * Ws[f * 9];
#pragma unroll
        for (int j = 0; j < 8; j++) sl += bb[j] * Ws[f * 9 + 1 + j];
        sum += sl;
    }
#pragma unroll
    for (int off = 16; off; off >>= 1)
        sum += __shfl_xor_sync(0xffffffffu, sum, off);
    if (lane == 0) out[n] = sum;
}

// ---------------- launch ------------------------------------------------------
extern "C" void kernel_launch(void* const* d_in, const int* in_sizes, int n_in,
                              void* d_out, int out_size) {
    const float* x    = (const float*)d_in[0];
    const float* freq = (const float*)d_in[1];
    const float* bw0  = (const float*)d_in[2];
    const float* sw0  = (const float*)d_in[3];
    const float* ss0  = (const float*)d_in[4];
    const float* bw1  = (const float*)d_in[5];
    const float* sw1  = (const float*)d_in[6];
    const float* ss1  = (const float*)d_in[7];
    const float* bw2  = (const float*)d_in[8];
    const float* sw2  = (const float*)d_in[9];
    const float* ss2  = (const float*)d_in[10];
    const float* bw3  = (const float*)d_in[11];
    const float* sw3  = (const float*)d_in[12];
    const float* ss3  = (const float*)d_in[13];
    float* out = (float*)d_out;

    float *bufA, *bufB, *w3;
    __half *W0, *W1, *W2;
    cudaGetSymbolAddress((void**)&bufA, g_bufA);
    cudaGetSymbolAddress((void**)&bufB, g_bufB);
    cudaGetSymbolAddress((void**)&W0, g_W0);
    cudaGetSymbolAddress((void**)&W1, g_W1);
    cudaGetSymbolAddress((void**)&W2, g_W2);
    cudaGetSymbolAddress((void**)&w3, g_w3);

    const int SMEM = 184320;
    cudaFuncSetAttribute(kan_hmma<32>,  cudaFuncAttributeMaxDynamicSharedMemorySize, SMEM);
    cudaFuncSetAttribute(kan_hmma<256>, cudaFuncAttributeMaxDynamicSharedMemorySize, SMEM);

    // [0] all weight prep in one launch
    prep_all<<<4905, 256>>>(bw0, sw0, ss0, bw1, sw1, ss1, bw2, sw2, ss2,
                            bw3, sw3, ss3, W0, W1, W2, w3);
    // [1] encoding
    encode_kernel<<<(N_PTS * 16) / 256, 256>>>(x, freq, bufA);

    // [2] layer 0
    kan_hmma<32><<<N_PTS / 64, 512, SMEM>>>(bufA, W0, bufB);
    // [3] layer 1  (<- ncu capture slot)
    kan_hmma<256><<<N_PTS / 64, 512, SMEM>>>(bufB, W1, bufA);
    // [4] layer 2
    kan_hmma<256><<<N_PTS / 64, 512, SMEM>>>(bufA, W2, bufB);
    // [5] last layer
    kan_last<<<N_PTS / 8, 256>>>(bufB, w3, out);
}

// round 15
// speedup vs baseline: 2.7247x; 1.0841x over previous
#include <cuda_runtime.h>
#include <cuda_fp16.h>
#include <math.h>
#include <stdint.h>

#define N_PTS 32768
typedef uint32_t u32;

// ---------------- scratch (device globals; no allocations allowed) ----------
__device__ float g_bufA[N_PTS * 256];
__device__ float g_bufB[N_PTS * 256];
__device__ __align__(16) __half g_W0[256 * 288];
__device__ __align__(16) __half g_W1[256 * 2304];
__device__ __align__(16) __half g_W2[256 * 2304];
__device__ float g_w3[2304];

// ---------------- PTX helpers (compute_80-era, arch-neutral) -----------------
__device__ __forceinline__ u32 smem_u32(const void* p) {
    u32 a;
    asm("{ .reg .u64 t; cvta.to.shared.u64 t, %1; cvt.u32.u64 %0, t; }"
        : "=r"(a) : "l"(p));
    return a;
}
__device__ __forceinline__ void ldsm_x4(u32* r, u32 addr) {
    asm volatile("ldmatrix.sync.aligned.m8n8.x4.shared.b16 {%0,%1,%2,%3}, [%4];"
                 : "=r"(r[0]), "=r"(r[1]), "=r"(r[2]), "=r"(r[3]) : "r"(addr));
}
__device__ __forceinline__ void mma_f16(float* c, const u32* a, const u32* b) {
    asm volatile(
        "mma.sync.aligned.m16n8k16.row.col.f32.f16.f16.f32 "
        "{%0,%1,%2,%3}, {%4,%5,%6,%7}, {%8,%9}, {%0,%1,%2,%3};"
        : "+f"(c[0]), "+f"(c[1]), "+f"(c[2]), "+f"(c[3])
        : "r"(a[0]), "r"(a[1]), "r"(a[2]), "r"(a[3]), "r"(b[0]), "r"(b[1]));
}
__device__ __forceinline__ void cp16(u32 dst, const void* src) {
    asm volatile("cp.async.cg.shared.global [%0], [%1], 16;"
                 :: "r"(dst), "l"(src) : "memory");
}

// ---------------- closed-form cubic B-spline (uniform knots) -----------------
__device__ __forceinline__ void bspline8(float t, float* bb) {
    float u = (t + 2.2f) * 2.5f;
    float fj = floorf(u);
    int jc = (int)fj;
    float w = u - fj;
    float om = 1.0f - w;
    float w2 = w * w, w3 = w2 * w;
    float p0 = om * om * om * (1.0f / 6.0f);
    float p1 = (3.0f * w3 - 6.0f * w2 + 4.0f) * (1.0f / 6.0f);
    float p2 = (-3.0f * w3 + 3.0f * w2 + 3.0f * w + 1.0f) * (1.0f / 6.0f);
    float p3 = w3 * (1.0f / 6.0f);
#pragma unroll
    for (int i = 0; i < 8; i++) {
        int m = i - jc + 3;
        float v = (m == 0) ? p0 : (m == 1) ? p1 : (m == 2) ? p2 : (m == 3) ? p3 : 0.0f;
        bb[i] = v;
    }
}
__device__ __forceinline__ float silu_f(float v) {
    return v * (1.0f / (1.0f + __expf(-v)));
}

// ---------------- fused weight prep (single launch) --------------------------
// K layout PERMUTED per 144-chunk: k = c*144 + j*16 + fl, feature f = c*16+fl.
__device__ __forceinline__ void prep_one(const float* bw, const float* sw,
                                         const float* ss, __half* W,
                                         int F, int idx) {
    int K = 9 * F;
    if (idx >= 256 * K) return;
    int o = idx / K, k = idx - o * K;
    int c = k / 144, r = k - c * 144;
    int j = r >> 4, fl = r & 15;
    int f = c * 16 + fl;
    float v = (j == 0) ? bw[o * F + f] : sw[(o * F + f) * 8 + (j - 1)] * ss[o * F + f];
    W[idx] = __float2half_rn(v);
}
__global__ void prep_all(const float* __restrict__ bw0, const float* __restrict__ sw0, const float* __restrict__ ss0,
                         const float* __restrict__ bw1, const float* __restrict__ sw1, const float* __restrict__ ss1,
                         const float* __restrict__ bw2, const float* __restrict__ sw2, const float* __restrict__ ss2,
                         const float* __restrict__ bw3, const float* __restrict__ sw3, const float* __restrict__ ss3,
                         __half* __restrict__ W0, __half* __restrict__ W1, __half* __restrict__ W2,
                         float* __restrict__ w3) {
    int b = blockIdx.x, t = threadIdx.x;
    if (b < 288) {
        prep_one(bw0, sw0, ss0, W0, 32, b * 256 + t);
    } else if (b < 2592) {
        prep_one(bw1, sw1, ss1, W1, 256, (b - 288) * 256 + t);
    } else if (b < 4896) {
        prep_one(bw2, sw2, ss2, W2, 256, (b - 2592) * 256 + t);
    } else {
        int k = (b - 4896) * 256 + t;
        if (k < 2304) {
            int f = k / 9, j = k - f * 9;
            w3[k] = (j == 0) ? bw3[f] : sw3[f * 8 + (j - 1)] * ss3[f];
        }
    }
}

// ---------------- positional encoding ---------------------------------------
__global__ void encode_kernel(const float* __restrict__ x,
                              const float* __restrict__ freq,
                              float* __restrict__ h0) {
    int idx = blockIdx.x * blockDim.x + threadIdx.x;
    if (idx >= N_PTS * 16) return;
    int n = idx >> 4, j = idx & 15;
    float enc = x[n] * freq[j];
    double ed = (double)enc;
    double q = rint(ed * 0.15915494309189535);
    double rd = fma(-q, 6.283185307179586, ed);
    float r = (float)rd;
    float s, c;
    __sincosf(r, &s, &c);
    h0[n * 32 + j] = s;
    h0[n * 32 + 16 + j] = c;
}

// ---------------- smem swizzle: row stride 288 B (18 x 16B units) ------------
__device__ __forceinline__ u32 swz_off(int row, int u) {
    if (u < 16) return (u32)(row * 288 + ((u * 16) ^ ((row & 7) * 16)));
    return (u32)(row * 288 + 256 + (((u ^ row) & 1) * 16));
}

// ---------------- fused HMMA KAN layer, 512 threads, 2-stage pipeline --------
// Single fp16 term. CTA tile: 128 rows x 256 cols. K chunks of 144 (k=j*16+fl).
// 16 warps: 2 m-groups x 8 n-groups, warp tile 64x32 (4 m-frags, 16 mma / 6 ldsm).
// Stage (110592 B): A@0 (36864) W@36864 (73728). Two stages = 221184 B.
template <int F>
__global__ void __launch_bounds__(512, 1)
kan_hmma(const float* __restrict__ hin, const __half* __restrict__ Wg,
         float* __restrict__ out) {
    constexpr int K = 9 * F, NCH = K / 144;
    constexpr u32 STG = 110592;
    constexpr u32 AO = 0, WO = 36864;
    extern __shared__ __align__(16) char smem[];
    const u32 sbase = smem_u32(smem);

    const int tid = threadIdx.x;
    const int lane = tid & 31, warp = tid >> 5;
    const int wm = (warp & 1) * 64;              // 2 m-groups of 64 rows
    const int wn = (warp >> 1) * 32;             // 8 n-groups of 32 cols
    const int row0 = blockIdx.x * 128;

    int rowA[4], rowB[2];
    const int bitA = lane >> 4;
    const int bitB = (lane >> 3) & 1;
#pragma unroll
    for (int mi = 0; mi < 4; mi++) rowA[mi] = wm + mi * 16 + (lane & 15);
#pragma unroll
    for (int jj = 0; jj < 2; jj++) rowB[jj] = wn + jj * 16 + (lane & 7) + ((lane >> 4) << 3);

    float acc[4][4][4];
#pragma unroll
    for (int mi = 0; mi < 4; mi++)
#pragma unroll
        for (int nf = 0; nf < 4; nf++)
#pragma unroll
            for (int q = 0; q < 4; q++) acc[mi][nf][q] = 0.0f;

    // ---- helpers
    auto issueW = [&](int c, u32 sb) {
#pragma unroll
        for (int i = 0; i < 9; i++) {
            int u = tid + 512 * i;
            int row = u / 18, pos = u - row * 18;
            size_t gi = ((size_t)row * K + c * 144) / 8 + pos;
            cp16(sbase + sb + WO + swz_off(row, pos),
                 reinterpret_cast<const uint4*>(Wg) + gi);
        }
    };
    auto storeA = [&](float t, int fl, int row, u32 sb) {
        float v[9];
        v[0] = silu_f(t);
        bspline8(t, v + 1);
        const int ub = fl >> 3, bo = (fl & 7) * 2;
#pragma unroll
        for (int j = 0; j < 9; j++) {
            u32 off = swz_off(row, 2 * j + ub) + bo;
            *reinterpret_cast<__half*>(smem + sb + AO + off) = __float2half_rn(v[j]);
        }
    };
    // 4 A-items per thread: id = tid + 512*i -> fl = id&15, row = id>>4 (0..127)
    int flI[4], rwI[4];
#pragma unroll
    for (int i = 0; i < 4; i++) {
        int id = tid + 512 * i;
        flI[i] = id & 15;
        rwI[i] = id >> 4;
    }

    // ---- prologue: fill stage 0
    {
        float p[4];
#pragma unroll
        for (int i = 0; i < 4; i++)
            p[i] = hin[(size_t)(row0 + rwI[i]) * F + flI[i]];
        issueW(0, 0);
        asm volatile("cp.async.commit_group;" ::: "memory");
#pragma unroll
        for (int i = 0; i < 4; i++) storeA(p[i], flI[i], rwI[i], 0);
    }

    for (int c = 0; c < NCH; c++) {
        const u32 sb = (u32)(c & 1) * STG;
        const u32 sbn = (u32)((c + 1) & 1) * STG;
        asm volatile("cp.async.wait_group 0;" ::: "memory");
        __syncthreads();                          // W(c),A(c) ready; stage sbn free
        const bool more = (c + 1 < NCH);
        float t4[4] = {0.0f, 0.0f, 0.0f, 0.0f};
        if (more) {
            // prefetch next-chunk activations FIRST (in flight under mma loop)
#pragma unroll
            for (int i = 0; i < 4; i++)
                t4[i] = hin[(size_t)(row0 + rwI[i]) * F + (c + 1) * 16 + flI[i]];
            issueW(c + 1, sbn);
            asm volatile("cp.async.commit_group;" ::: "memory");
        }
#pragma unroll
        for (int ks = 0; ks < 9; ks++) {
            u32 ah[4][4], b[2][4];
#pragma unroll
            for (int mi = 0; mi < 4; mi++)
                ldsm_x4(ah[mi], sbase + sb + AO + swz_off(rowA[mi], 2 * ks + bitA));
#pragma unroll
            for (int jj = 0; jj < 2; jj++)
                ldsm_x4(b[jj], sbase + sb + WO + swz_off(rowB[jj], 2 * ks + bitB));
#pragma unroll
            for (int mi = 0; mi < 4; mi++)
#pragma unroll
                for (int nf = 0; nf < 4; nf++)
                    mma_f16(acc[mi][nf], ah[mi], &b[nf >> 1][(nf & 1) * 2]);
            // consume prefetched activations late (loads landed by now)
            if (more && ks >= 5) storeA(t4[ks - 5], flI[ks - 5], rwI[ks - 5], sbn);
        }
    }
    // ---- epilogue: c-frag direct stores
#pragma unroll
    for (int mi = 0; mi < 4; mi++)
#pragma unroll
        for (int nf = 0; nf < 4; nf++) {
            int r0 = row0 + wm + mi * 16 + (lane >> 2);
            int cc = wn + nf * 8 + (lane & 3) * 2;
            *reinterpret_cast<float2*>(&out[(size_t)r0 * 256 + cc]) =
                make_float2(acc[mi][nf][0], acc[mi][nf][1]);
            *reinterpret_cast<float2*>(&out[(size_t)(r0 + 8) * 256 + cc]) =
                make_float2(acc[mi][nf][2], acc[mi][nf][3]);
        }
}

// ---------------- last layer: O = 1 ------------------------------------------
__global__ void kan_last(const float* __restrict__ hin,
                         const float* __restrict__ W,
                         float* __restrict__ out) {
    __shared__ float Ws[2304];
    int tid = threadIdx.x;
#pragma unroll
    for (int i = tid; i < 2304; i += 256) Ws[i] = W[i];
    __syncthreads();
    int warp = tid >> 5, lane = tid & 31;
    int n = blockIdx.x * 8 + warp;
    float sum = 0.0f;
#pragma unroll
    for (int ff = 0; ff < 8; ff++) {
        int f = ff * 32 + lane;
        float t = hin[n * 256 + f];
        float bb[8];
        bspline8(t, bb);
        float sl = silu_f(t) * Ws[f * 9];
#pragma unroll
        for (int j = 0; j < 8; j++) sl += bb[j] * Ws[f * 9 + 1 + j];
        sum += sl;
    }
#pragma unroll
    for (int off = 16; off; off >>= 1)
        sum += __shfl_xor_sync(0xffffffffu, sum, off);
    if (lane == 0) out[n] = sum;
}

// ---------------- launch ------------------------------------------------------
extern "C" void kernel_launch(void* const* d_in, const int* in_sizes, int n_in,
                              void* d_out, int out_size) {
    const float* x    = (const float*)d_in[0];
    const float* freq = (const float*)d_in[1];
    const float* bw0  = (const float*)d_in[2];
    const float* sw0  = (const float*)d_in[3];
    const float* ss0  = (const float*)d_in[4];
    const float* bw1  = (const float*)d_in[5];
    const float* sw1  = (const float*)d_in[6];
    const float* ss1  = (const float*)d_in[7];
    const float* bw2  = (const float*)d_in[8];
    const float* sw2  = (const float*)d_in[9];
    const float* ss2  = (const float*)d_in[10];
    const float* bw3  = (const float*)d_in[11];
    const float* sw3  = (const float*)d_in[12];
    const float* ss3  = (const float*)d_in[13];
    float* out = (float*)d_out;

    float *bufA, *bufB, *w3;
    __half *W0, *W1, *W2;
    cudaGetSymbolAddress((void**)&bufA, g_bufA);
    cudaGetSymbolAddress((void**)&bufB, g_bufB);
    cudaGetSymbolAddress((void**)&W0, g_W0);
    cudaGetSymbolAddress((void**)&W1, g_W1);
    cudaGetSymbolAddress((void**)&W2, g_W2);
    cudaGetSymbolAddress((void**)&w3, g_w3);

    const int SMEM = 221184;
    cudaFuncSetAttribute(kan_hmma<32>,  cudaFuncAttributeMaxDynamicSharedMemorySize, SMEM);
    cudaFuncSetAttribute(kan_hmma<256>, cudaFuncAttributeMaxDynamicSharedMemorySize, SMEM);

    // [0] all weight prep in one launch
    prep_all<<<4905, 256>>>(bw0, sw0, ss0, bw1, sw1, ss1, bw2, sw2, ss2,
                            bw3, sw3, ss3, W0, W1, W2, w3);
    // [1] encoding
    encode_kernel<<<(N_PTS * 16) / 256, 256>>>(x, freq, bufA);

    // [2] layer 0
    kan_hmma<32><<<N_PTS / 128, 512, SMEM>>>(bufA, W0, bufB);
    // [3] layer 1  (<- ncu capture slot)
    kan_hmma<256><<<N_PTS / 128, 512, SMEM>>>(bufB, W1, bufA);
    // [4] layer 2
    kan_hmma<256><<<N_PTS / 128, 512, SMEM>>>(bufA, W2, bufB);
    // [5] last layer
    kan_last<<<N_PTS / 8, 256>>>(bufB, w3, out);
}

// round 16
// speedup vs baseline: 3.2055x; 1.1765x over previous
#include <cuda_runtime.h>
#include <cuda_fp16.h>
#include <math.h>
#include <stdint.h>

#define N_PTS 32768
typedef uint32_t u32;

// ---------------- scratch (device globals; no allocations allowed) ----------
__device__ float g_bufA[N_PTS * 256];
__device__ float g_bufB[N_PTS * 256];
__device__ __align__(16) __half g_W0[256 * 288];
__device__ __align__(16) __half g_W1[256 * 2304];
__device__ __align__(16) __half g_W2[256 * 2304];
__device__ float g_w3[2304];

// ---------------- PTX helpers (compute_80-era, arch-neutral) -----------------
__device__ __forceinline__ u32 smem_u32(const void* p) {
    u32 a;
    asm("{ .reg .u64 t; cvta.to.shared.u64 t, %1; cvt.u32.u64 %0, t; }"
        : "=r"(a) : "l"(p));
    return a;
}
__device__ __forceinline__ void ldsm_x4(u32* r, u32 addr) {
    asm volatile("ldmatrix.sync.aligned.m8n8.x4.shared.b16 {%0,%1,%2,%3}, [%4];"
                 : "=r"(r[0]), "=r"(r[1]), "=r"(r[2]), "=r"(r[3]) : "r"(addr));
}
__device__ __forceinline__ void mma_f16(float* c, const u32* a, const u32* b) {
    asm volatile(
        "mma.sync.aligned.m16n8k16.row.col.f32.f16.f16.f32 "
        "{%0,%1,%2,%3}, {%4,%5,%6,%7}, {%8,%9}, {%0,%1,%2,%3};"
        : "+f"(c[0]), "+f"(c[1]), "+f"(c[2]), "+f"(c[3])
        : "r"(a[0]), "r"(a[1]), "r"(a[2]), "r"(a[3]), "r"(b[0]), "r"(b[1]));
}
__device__ __forceinline__ void cp16(u32 dst, const void* src) {
    asm volatile("cp.async.cg.shared.global [%0], [%1], 16;"
                 :: "r"(dst), "l"(src) : "memory");
}

// ---------------- closed-form cubic B-spline (uniform knots) -----------------
__device__ __forceinline__ void bspline8(float t, float* bb) {
    float u = (t + 2.2f) * 2.5f;
    float fj = floorf(u);
    int jc = (int)fj;
    float w = u - fj;
    float om = 1.0f - w;
    float w2 = w * w, w3 = w2 * w;
    float p0 = om * om * om * (1.0f / 6.0f);
    float p1 = (3.0f * w3 - 6.0f * w2 + 4.0f) * (1.0f / 6.0f);
    float p2 = (-3.0f * w3 + 3.0f * w2 + 3.0f * w + 1.0f) * (1.0f / 6.0f);
    float p3 = w3 * (1.0f / 6.0f);
#pragma unroll
    for (int i = 0; i < 8; i++) {
        int m = i - jc + 3;
        float v = (m == 0) ? p0 : (m == 1) ? p1 : (m == 2) ? p2 : (m == 3) ? p3 : 0.0f;
        bb[i] = v;
    }
}
__device__ __forceinline__ float silu_f(float v) {
    return v * (1.0f / (1.0f + __expf(-v)));
}

// ---------------- fused weight prep (single launch) --------------------------
// K layout PERMUTED per 144-chunk: k = c*144 + j*16 + fl, feature f = c*16+fl.
__device__ __forceinline__ void prep_one(const float* bw, const float* sw,
                                         const float* ss, __half* W,
                                         int F, int idx) {
    int K = 9 * F;
    if (idx >= 256 * K) return;
    int o = idx / K, k = idx - o * K;
    int c = k / 144, r = k - c * 144;
    int j = r >> 4, fl = r & 15;
    int f = c * 16 + fl;
    float v = (j == 0) ? bw[o * F + f] : sw[(o * F + f) * 8 + (j - 1)] * ss[o * F + f];
    W[idx] = __float2half_rn(v);
}
__global__ void prep_all(const float* __restrict__ bw0, const float* __restrict__ sw0, const float* __restrict__ ss0,
                         const float* __restrict__ bw1, const float* __restrict__ sw1, const float* __restrict__ ss1,
                         const float* __restrict__ bw2, const float* __restrict__ sw2, const float* __restrict__ ss2,
                         const float* __restrict__ bw3, const float* __restrict__ sw3, const float* __restrict__ ss3,
                         __half* __restrict__ W0, __half* __restrict__ W1, __half* __restrict__ W2,
                         float* __restrict__ w3) {
    int b = blockIdx.x, t = threadIdx.x;
    if (b < 288) {
        prep_one(bw0, sw0, ss0, W0, 32, b * 256 + t);
    } else if (b < 2592) {
        prep_one(bw1, sw1, ss1, W1, 256, (b - 288) * 256 + t);
    } else if (b < 4896) {
        prep_one(bw2, sw2, ss2, W2, 256, (b - 2592) * 256 + t);
    } else {
        int k = (b - 4896) * 256 + t;
        if (k < 2304) {
            int f = k / 9, j = k - f * 9;
            w3[k] = (j == 0) ? bw3[f] : sw3[f * 8 + (j - 1)] * ss3[f];
        }
    }
}

// ---------------- positional encoding ---------------------------------------
__global__ void encode_kernel(const float* __restrict__ x,
                              const float* __restrict__ freq,
                              float* __restrict__ h0) {
    int idx = blockIdx.x * blockDim.x + threadIdx.x;
    if (idx >= N_PTS * 16) return;
    int n = idx >> 4, j = idx & 15;
    float enc = x[n] * freq[j];
    double ed = (double)enc;
    double q = rint(ed * 0.15915494309189535);
    double rd = fma(-q, 6.283185307179586, ed);
    float r = (float)rd;
    float s, c;
    __sincosf(r, &s, &c);
    h0[n * 32 + j] = s;
    h0[n * 32 + 16 + j] = c;
}

// ---------------- smem swizzle: row stride 288 B (18 x 16B units) ------------
__device__ __forceinline__ u32 swz_off(int row, int u) {
    if (u < 16) return (u32)(row * 288 + ((u * 16) ^ ((row & 7) * 16)));
    return (u32)(row * 288 + 256 + (((u ^ row) & 1) * 16));
}

// ---------------- fused HMMA KAN layer, 512 thr, 2 CTAs/SM -------------------
// Single fp16 term. CTA tile: 64 rows x 256 cols. K chunks of 144 (k=j*16+fl).
// 16 warps: 2 m-groups x 8 n-groups, warp tile 32x32.
// Single stage (92160 B): A@0 W@18432 -> 2 CTAs/SM = 8 warps/SMSP.
// Cross-CTA overlap covers the serialized produce/load phase; activation LDGs
// are prefetched during the previous chunk's MMA loop.
template <int F>
__global__ void __launch_bounds__(512, 2)
kan_hmma(const float* __restrict__ hin, const __half* __restrict__ Wg,
         float* __restrict__ out) {
    constexpr int K = 9 * F, NCH = K / 144;
    constexpr u32 AO = 0, WO = 18432;
    extern __shared__ __align__(16) char smem[];
    const u32 sbase = smem_u32(smem);

    const int tid = threadIdx.x;
    const int lane = tid & 31, warp = tid >> 5;
    const int wm = (warp & 1) * 32;              // 2 m-groups of 32 rows
    const int wn = (warp >> 1) * 32;             // 8 n-groups of 32 cols
    const int row0 = blockIdx.x * 64;

    int rowA[2], rowB[2];
    const int bitA = lane >> 4;
    const int bitB = (lane >> 3) & 1;
#pragma unroll
    for (int mi = 0; mi < 2; mi++) rowA[mi] = wm + mi * 16 + (lane & 15);
#pragma unroll
    for (int jj = 0; jj < 2; jj++) rowB[jj] = wn + jj * 16 + (lane & 7) + ((lane >> 4) << 3);

    // 2 A-items per thread: id = tid + 512*i -> fl = id&15, row = id>>4 (0..63)
    const int fl0 = tid & 15,          rA0 = tid >> 4;
    const int fl1 = (tid + 512) & 15,  rA1 = (tid + 512) >> 4;

    float acc[2][4][4];
#pragma unroll
    for (int mi = 0; mi < 2; mi++)
#pragma unroll
        for (int nf = 0; nf < 4; nf++)
#pragma unroll
            for (int q = 0; q < 4; q++) acc[mi][nf][q] = 0.0f;

    // ---- helpers
    auto issueW = [&](int c) {
#pragma unroll
        for (int i = 0; i < 9; i++) {
            int u = tid + 512 * i;
            int row = u / 18, pos = u - row * 18;
            size_t gi = ((size_t)row * K + c * 144) / 8 + pos;
            cp16(sbase + WO + swz_off(row, pos),
                 reinterpret_cast<const uint4*>(Wg) + gi);
        }
    };
    auto storeA = [&](float t, int fl, int row) {
        float v[9];
        v[0] = silu_f(t);
        bspline8(t, v + 1);
        const int ub = fl >> 3, bo = (fl & 7) * 2;
#pragma unroll
        for (int j = 0; j < 9; j++) {
            u32 off = swz_off(row, 2 * j + ub) + bo;
            *reinterpret_cast<__half*>(smem + AO + off) = __float2half_rn(v[j]);
        }
    };

    // ---- prologue: prefetch chunk-0 activations
    float t0 = hin[(size_t)(row0 + rA0) * F + fl0];
    float t1 = hin[(size_t)(row0 + rA1) * F + fl1];

    for (int c = 0; c < NCH; c++) {
        __syncthreads();                          // previous MMA done with stage
        issueW(c);
        asm volatile("cp.async.commit_group;" ::: "memory");
        storeA(t0, fl0, rA0);
        storeA(t1, fl1, rA1);
        asm volatile("cp.async.wait_group 0;" ::: "memory");
        __syncthreads();                          // W(c)+A(c) visible
        if (c + 1 < NCH) {
            // prefetch next-chunk activations (in flight under the MMA loop)
            t0 = hin[(size_t)(row0 + rA0) * F + (c + 1) * 16 + fl0];
            t1 = hin[(size_t)(row0 + rA1) * F + (c + 1) * 16 + fl1];
        }
#pragma unroll
        for (int ks = 0; ks < 9; ks++) {
            u32 ah[2][4], b[2][4];
#pragma unroll
            for (int mi = 0; mi < 2; mi++)
                ldsm_x4(ah[mi], sbase + AO + swz_off(rowA[mi], 2 * ks + bitA));
#pragma unroll
            for (int jj = 0; jj < 2; jj++)
                ldsm_x4(b[jj], sbase + WO + swz_off(rowB[jj], 2 * ks + bitB));
#pragma unroll
            for (int mi = 0; mi < 2; mi++)
#pragma unroll
                for (int nf = 0; nf < 4; nf++)
                    mma_f16(acc[mi][nf], ah[mi], &b[nf >> 1][(nf & 1) * 2]);
        }
    }
    // ---- epilogue: c-frag direct stores
#pragma unroll
    for (int mi = 0; mi < 2; mi++)
#pragma unroll
        for (int nf = 0; nf < 4; nf++) {
            int r0 = row0 + wm + mi * 16 + (lane >> 2);
            int cc = wn + nf * 8 + (lane & 3) * 2;
            *reinterpret_cast<float2*>(&out[(size_t)r0 * 256 + cc]) =
                make_float2(acc[mi][nf][0], acc[mi][nf][1]);
            *reinterpret_cast<float2*>(&out[(size_t)(r0 + 8) * 256 + cc]) =
                make_float2(acc[mi][nf][2], acc[mi][nf][3]);
        }
}

// ---------------- last layer: O = 1 ------------------------------------------
__global__ void kan_last(const float* __restrict__ hin,
                         const float* __restrict__ W,
                         float* __restrict__ out) {
    __shared__ float Ws[2304];
    int tid = threadIdx.x;
#pragma unroll
    for (int i = tid; i < 2304; i += 256) Ws[i] = W[i];
    __syncthreads();
    int warp = tid >> 5, lane = tid & 31;
    int n = blockIdx.x * 8 + warp;
    float sum = 0.0f;
#pragma unroll
    for (int ff = 0; ff < 8; ff++) {
        int f = ff * 32 + lane;
        float t = hin[n * 256 + f];
        float bb[8];
        bspline8(t, bb);
        float sl = silu_f(t) * Ws[f * 9];
#pragma unroll
        for (int j = 0; j < 8; j++) sl += bb[j] * Ws[f * 9 + 1 + j];
        sum += sl;
    }
#pragma unroll
    for (int off = 16; off; off >>= 1)
        sum += __shfl_xor_sync(0xffffffffu, sum, off);
    if (lane == 0) out[n] = sum;
}

// ---------------- launch ------------------------------------------------------
extern "C" void kernel_launch(void* const* d_in, const int* in_sizes, int n_in,
                              void* d_out, int out_size) {
    const float* x    = (const float*)d_in[0];
    const float* freq = (const float*)d_in[1];
    const float* bw0  = (const float*)d_in[2];
    const float* sw0  = (const float*)d_in[3];
    const float* ss0  = (const float*)d_in[4];
    const float* bw1  = (const float*)d_in[5];
    const float* sw1  = (const float*)d_in[6];
    const float* ss1  = (const float*)d_in[7];
    const float* bw2  = (const float*)d_in[8];
    const float* sw2  = (const float*)d_in[9];
    const float* ss2  = (const float*)d_in[10];
    const float* bw3  = (const float*)d_in[11];
    const float* sw3  = (const float*)d_in[12];
    const float* ss3  = (const float*)d_in[13];
    float* out = (float*)d_out;

    float *bufA, *bufB, *w3;
    __half *W0, *W1, *W2;
    cudaGetSymbolAddress((void**)&bufA, g_bufA);
    cudaGetSymbolAddress((void**)&bufB, g_bufB);
    cudaGetSymbolAddress((void**)&W0, g_W0);
    cudaGetSymbolAddress((void**)&W1, g_W1);
    cudaGetSymbolAddress((void**)&W2, g_W2);
    cudaGetSymbolAddress((void**)&w3, g_w3);

    const int SMEM = 92160;
    cudaFuncSetAttribute(kan_hmma<32>,  cudaFuncAttributeMaxDynamicSharedMemorySize, SMEM);
    cudaFuncSetAttribute(kan_hmma<256>, cudaFuncAttributeMaxDynamicSharedMemorySize, SMEM);

    // [0] all weight prep in one launch
    prep_all<<<4905, 256>>>(bw0, sw0, ss0, bw1, sw1, ss1, bw2, sw2, ss2,
                            bw3, sw3, ss3, W0, W1, W2, w3);
    // [1] encoding
    encode_kernel<<<(N_PTS * 16) / 256, 256>>>(x, freq, bufA);

    // [2] layer 0
    kan_hmma<32><<<N_PTS / 64, 512, SMEM>>>(bufA, W0, bufB);
    // [3] layer 1  (<- ncu capture slot)
    kan_hmma<256><<<N_PTS / 64, 512, SMEM>>>(bufB, W1, bufA);
    // [4] layer 2
    kan_hmma<256><<<N_PTS / 64, 512, SMEM>>>(bufA, W2, bufB);
    // [5] last layer
    kan_last<<<N_PTS / 8, 256>>>(bufB, w3, out);
}